// round 5
// baseline (speedup 1.0000x reference)
#include <cuda_runtime.h>

#define L_LEN   4096
#define N_ROWS  4096
#define TILES   (L_LEN / 32)      // 128 tiles of 32 float4 per row
#define TPB     128
#define WPC     (TPB / 32)        // 4 rows per CTA
#define FULLM   0xFFFFFFFFu

// Fast, numerically safe softplus: max(x,0) + log(1 + e^{-|x|})
__device__ __forceinline__ float softplus_f(float x) {
    return fmaxf(x, 0.0f) + __logf(1.0f + __expf(-fabsf(x)));
}

__global__ __launch_bounds__(TPB)
void socnet_kernel(const float* __restrict__ X,
                   const float* __restrict__ SC,
                   const float* __restrict__ w_init1,
                   const float* __restrict__ b_init1,
                   const float* __restrict__ w_init2,
                   const float* __restrict__ b_init2,
                   const float* __restrict__ w_eta1,
                   const float* __restrict__ b_eta1,
                   const float* __restrict__ w_eta2,
                   const float* __restrict__ b_eta2,
                   float* __restrict__ out) {
    const int lane = threadIdx.x & 31;
    const int row  = blockIdx.x * WPC + (threadIdx.x >> 5);

    const float4* __restrict__ Xr = reinterpret_cast<const float4*>(X) + (size_t)row * L_LEN;
    float4* __restrict__ Or       = reinterpret_cast<float4*>(out)     + (size_t)row * L_LEN;

    // Per-row scalars: SC = [Q, eta0, R, cap]
    const float Q    = SC[row * 4 + 0];
    const float eta0 = SC[row * 4 + 1];
    const float R    = SC[row * 4 + 2];
    const float cap  = SC[row * 4 + 3];

    const float we0 = w_eta1[0];
    const float we1 = w_eta1[1];
    const float be1 = b_eta1[0];
    const float we2 = w_eta2[0];
    const float be2 = b_eta2[0];

    const float dscale = eta0 / (3600.0f * Q);

    // ---- Tile 0 load + per-element delta_eta ----
    float4 x0 = Xr[lane];
    float pI = x0.y, pT = x0.z, pU = x0.w;
    float pde = we2 * softplus_f(we0 * pI + we1 * pT + be1) + be2;

    // ---- soc_init (uniform across warp, from element 0) ----
    const float I0 = __shfl_sync(FULLM, pI, 0);
    const float T0 = __shfl_sync(FULLM, pT, 0);
    const float U0 = __shfl_sync(FULLM, pU, 0);
    float z = w_init1[0] * I0 + w_init1[1] * T0
            + w_init1[2] * U0 + w_init1[3] * R + b_init1[0];
    const float soc = cap * (1.0f + (w_init2[0] * softplus_f(z) + b_init2[0]));

    // Running base = soc + prefix of all earlier tiles' increments
    float bx = soc, by = soc, bz = soc, bw = soc;

    #pragma unroll 2
    for (int it = 0; it < TILES; ++it) {
        // Pipeline: load next tile and its delta_eta
        float nI, nT, nU, nde;
        if (it < TILES - 1) {
            float4 xn = Xr[(it + 1) * 32 + lane];
            nI = xn.y; nT = xn.z; nU = xn.w;
            nde = we2 * softplus_f(we0 * nI + we1 * nT + be1) + be2;
        } else {
            nI = pI; nT = pT; nU = pU; nde = pde;
        }

        // Neighbor value at t+1: rotate-by-1 shfl; lane 0 contributes next tile's
        // first element so lane 31 receives it.
        const int src = (lane + 1) & 31;
        const float qI  = __shfl_sync(FULLM, (lane == 0) ? nI  : pI,  src);
        const float qT  = __shfl_sync(FULLM, (lane == 0) ? nT  : pT,  src);
        const float qU  = __shfl_sync(FULLM, (lane == 0) ? nU  : pU,  src);
        const float qde = __shfl_sync(FULLM, (lane == 0) ? nde : pde, src);

        const float dy = dscale * (1.0f + pde) * pI;
        float ex = dy * (qI - pI);
        float ey = dy * (qT - pT);
        float ez = dy * (qU - pU);
        float ew = dy * (qde - pde);
        if (it == TILES - 1 && lane == 31) {  // inc[L-1] does not exist
            ex = 0.f; ey = 0.f; ez = 0.f; ew = 0.f;
        }

        // Warp-inclusive scan of the 4 channels
        float sx = ex, sy = ey, sz = ez, sw = ew;
        #pragma unroll
        for (int d = 1; d < 32; d <<= 1) {
            float ax = __shfl_up_sync(FULLM, sx, d);
            float ay = __shfl_up_sync(FULLM, sy, d);
            float az = __shfl_up_sync(FULLM, sz, d);
            float aw = __shfl_up_sync(FULLM, sw, d);
            if (lane >= d) { sx += ax; sy += ay; sz += az; sw += aw; }
        }

        // out[t] = base + exclusive prefix = base + (S - e)
        float4 o;
        o.x = bx + (sx - ex);
        o.y = by + (sy - ey);
        o.z = bz + (sz - ez);
        o.w = bw + (sw - ew);
        Or[it * 32 + lane] = o;

        // Carry the tile total forward
        bx += __shfl_sync(FULLM, sx, 31);
        by += __shfl_sync(FULLM, sy, 31);
        bz += __shfl_sync(FULLM, sz, 31);
        bw += __shfl_sync(FULLM, sw, 31);

        pI = nI; pT = nT; pU = nU; pde = nde;
    }
}

extern "C" void kernel_launch(void* const* d_in, const int* in_sizes, int n_in,
                              void* d_out, int out_size) {
    const float* X       = (const float*)d_in[0];
    const float* SC      = (const float*)d_in[1];
    const float* w_init1 = (const float*)d_in[2];
    const float* b_init1 = (const float*)d_in[3];
    const float* w_init2 = (const float*)d_in[4];
    const float* b_init2 = (const float*)d_in[5];
    const float* w_eta1  = (const float*)d_in[6];
    const float* b_eta1  = (const float*)d_in[7];
    const float* w_eta2  = (const float*)d_in[8];
    const float* b_eta2  = (const float*)d_in[9];
    float* out = (float*)d_out;

    socnet_kernel<<<N_ROWS / WPC, TPB>>>(X, SC,
                                         w_init1, b_init1, w_init2, b_init2,
                                         w_eta1, b_eta1, w_eta2, b_eta2,
                                         out);
}

// round 6
// speedup vs baseline: 1.2292x; 1.2292x over previous
#include <cuda_runtime.h>
#include <cuda.h>
#include <cstdint>

#define L_LEN     4096
#define N_ROWS    4096
#define TPB       128
#define WPC       4                  // warps per CTA, one row per warp
#define GRID      (N_ROWS / WPC)     // 1024 CTAs
#define SEGS      32                 // 2KB segments per row
#define SEG_F4    128                // float4 per segment
#define SEG_BYTES 2048
#define ROW128    512                // 128B-rows per data row (4096*16/128)
#define FULLM     0xFFFFFFFFu

// Fast, numerically safe softplus: max(x,0) + log(1 + e^{-|x|})
__device__ __forceinline__ float softplus_f(float x) {
    return fmaxf(x, 0.0f) + __logf(1.0f + __expf(-fabsf(x)));
}

// SW128 swizzled byte offset of float4 element e within a 2KB tile
__device__ __forceinline__ int swz16(int e) {
    int b = e << 4;
    return b ^ ((b >> 3) & 0x70);
}

__device__ __forceinline__ uint32_t smem_u32(const void* p) {
    return (uint32_t)__cvta_generic_to_shared(p);
}
__device__ __forceinline__ void mbar_init(uint32_t a, uint32_t cnt) {
    asm volatile("mbarrier.init.shared.b64 [%0], %1;" :: "r"(a), "r"(cnt) : "memory");
}
__device__ __forceinline__ void mbar_expect_tx(uint32_t a, uint32_t bytes) {
    asm volatile("mbarrier.arrive.expect_tx.shared.b64 _, [%0], %1;"
                 :: "r"(a), "r"(bytes) : "memory");
}
__device__ __forceinline__ void mbar_wait(uint32_t a, uint32_t parity) {
    asm volatile(
        "{\n\t.reg .pred P;\n\t"
        "W_%=:\n\t"
        "mbarrier.try_wait.parity.acquire.cta.shared::cta.b64 P, [%0], %1;\n\t"
        "@!P bra W_%=;\n\t}"
        :: "r"(a), "r"(parity) : "memory");
}
__device__ __forceinline__ void tma_load_seg(uint32_t dst, const CUtensorMap* m,
                                             int y, uint32_t mbar) {
    asm volatile("cp.async.bulk.tensor.2d.shared::cta.global.tile.mbarrier::complete_tx::bytes "
                 "[%0], [%1, {%2, %3}], [%4];"
                 :: "r"(dst), "l"(m), "r"(0), "r"(y), "r"(mbar) : "memory");
}
__device__ __forceinline__ void tma_store_seg(const CUtensorMap* m, int y, uint32_t src) {
    asm volatile("cp.async.bulk.tensor.2d.global.shared::cta.tile.bulk_group "
                 "[%0, {%1, %2}], [%3];"
                 :: "l"(m), "r"(0), "r"(y), "r"(src) : "memory");
}

__global__ __launch_bounds__(TPB)
void socnet_tma(const __grid_constant__ CUtensorMap tmap_in,
                const __grid_constant__ CUtensorMap tmap_out,
                const float* __restrict__ SC,
                const float* __restrict__ w_init1, const float* __restrict__ b_init1,
                const float* __restrict__ w_init2, const float* __restrict__ b_init2,
                const float* __restrict__ w_eta1,  const float* __restrict__ b_eta1,
                const float* __restrict__ w_eta2,  const float* __restrict__ b_eta2) {
    __shared__ __align__(1024) float4 s_in [WPC][2][SEG_F4];
    __shared__ __align__(1024) float4 s_out[WPC][2][SEG_F4];
    __shared__ unsigned long long     s_mbar[WPC][2];

    const int lane = threadIdx.x & 31;
    const int wid  = threadIdx.x >> 5;
    const int row  = blockIdx.x * WPC + wid;
    const int ybase = row * ROW128;

    const float we0 = w_eta1[0], we1 = w_eta1[1], be1 = b_eta1[0];
    const float we2 = w_eta2[0], be2 = b_eta2[0];

    const uint32_t mb0 = smem_u32(&s_mbar[wid][0]);
    const uint32_t mb1 = smem_u32(&s_mbar[wid][1]);
    const uint32_t inb0  = smem_u32(&s_in[wid][0][0]);
    const uint32_t inb1  = smem_u32(&s_in[wid][1][0]);
    const uint32_t outb0 = smem_u32(&s_out[wid][0][0]);
    const uint32_t outb1 = smem_u32(&s_out[wid][1][0]);

    if (lane == 0) { mbar_init(mb0, 1); mbar_init(mb1, 1); }
    asm volatile("fence.proxy.async.shared::cta;" ::: "memory");
    __syncwarp();

    if (lane == 0) {
        mbar_expect_tx(mb0, SEG_BYTES);
        tma_load_seg(inb0, &tmap_in, ybase, mb0);
        mbar_expect_tx(mb1, SEG_BYTES);
        tma_load_seg(inb1, &tmap_in, ybase + 16, mb1);
    }
    uint32_t ph0 = 0, ph1 = 0;
    mbar_wait(mb0, 0); ph0 = 1;                 // seg 0 ready

    // Per-row scalars: SC = [Q, eta0, R, cap]; soc_init from element 0
    const float Q    = SC[row * 4 + 0];
    const float eta0 = SC[row * 4 + 1];
    const float R    = SC[row * 4 + 2];
    const float cap  = SC[row * 4 + 3];
    const float dscale = eta0 / (3600.0f * Q);
    {
        float4 x0 = s_in[wid][0][0];            // swz16(0)==0, broadcast
        float z = w_init1[0] * x0.y + w_init1[1] * x0.z
                + w_init1[2] * x0.w + w_init1[3] * R + b_init1[0];
        float soc = cap * (1.0f + (w_init2[0] * softplus_f(z) + b_init2[0]));
        // running base
        asm volatile("" ::: "memory");
        // (soc used below)
        // store into registers:
        // handled just after via bx..bw init
        // (kept inline for clarity)
        // --
        // init bases:
        // (fallthrough)
        // NOLINT
        // set:
        //
        // (nothing else)
        //
        // assign:
        //
        // done
        //
        // (see below)
        //
        // -- actual init:
        //
        // bx..bw
        //
        // (placed here to keep x0 live-range short)
        //
        // ---
        // real code:
        //
        // (continue)
        //
        // bases:
        //
        float bx = soc, by = soc, bz = soc, bw = soc;

        #pragma unroll 1
        for (int s = 0; s < SEGS; ++s) {
            const int b = s & 1;
            const char* ib  = (const char*)&s_in[wid][b][0];
            const char* ibN = (const char*)&s_in[wid][b ^ 1][0];

            if (s < SEGS - 1) {                 // wait seg s+1 (boundary source)
                if (b) { mbar_wait(mb0, ph0); ph0 ^= 1; }
                else   { mbar_wait(mb1, ph1); ph1 ^= 1; }
            }

            // Own 4 consecutive elements (conflict-free via SW128 swizzle)
            float I[4], T[4], U[4], de[4];
            #pragma unroll
            for (int k = 0; k < 4; ++k) {
                float4 x = *(const float4*)(ib + swz16(4 * lane + k));
                I[k] = x.y; T[k] = x.z; U[k] = x.w;
                de[k] = we2 * softplus_f(we0 * I[k] + we1 * T[k] + be1) + be2;
            }
            // Boundary = elem 0 of seg s+1 (stale/unused for final seg)
            float4 bnd = *(const float4*)(ibN);
            const float bde = we2 * softplus_f(we0 * bnd.y + we1 * bnd.z + be1) + be2;

            float nI  = __shfl_down_sync(FULLM, I[0], 1);
            float nT  = __shfl_down_sync(FULLM, T[0], 1);
            float nU  = __shfl_down_sync(FULLM, U[0], 1);
            float nde = __shfl_down_sync(FULLM, de[0], 1);
            if (lane == 31) { nI = bnd.y; nT = bnd.z; nU = bnd.w; nde = bde; }

            // Serial local exclusive prefixes; zero the nonexistent inc[L-1]
            const float lastmask =
                (s == SEGS - 1 && lane == 31) ? 0.0f : 1.0f;
            float px[4], py[4], pz[4], pw[4];
            float tx = 0.f, ty = 0.f, tz = 0.f, tw = 0.f;
            #pragma unroll
            for (int k = 0; k < 4; ++k) {
                px[k] = tx; py[k] = ty; pz[k] = tz; pw[k] = tw;
                const float xI = (k < 3) ? I[k + 1]  : nI;
                const float xT = (k < 3) ? T[k + 1]  : nT;
                const float xU = (k < 3) ? U[k + 1]  : nU;
                const float xd = (k < 3) ? de[k + 1] : nde;
                float dy = dscale * (1.0f + de[k]) * I[k];
                if (k == 3) dy *= lastmask;
                tx += dy * (xI - I[k]);
                ty += dy * (xT - T[k]);
                tz += dy * (xU - U[k]);
                tw += dy * (xd - de[k]);
            }

            // Inputs consumed -> refill this in-buffer with seg s+2
            __syncwarp();
            if (s + 2 < SEGS && lane == 0) {
                if (b) { mbar_expect_tx(mb1, SEG_BYTES);
                         tma_load_seg(inb1, &tmap_in, ybase + (s + 2) * 16, mb1); }
                else   { mbar_expect_tx(mb0, SEG_BYTES);
                         tma_load_seg(inb0, &tmap_in, ybase + (s + 2) * 16, mb0); }
            }

            // Warp scan of thread totals (once per 128 elements)
            float sx = tx, sy = ty, sz = tz, sw = tw;
            #pragma unroll
            for (int d = 1; d < 32; d <<= 1) {
                float ax = __shfl_up_sync(FULLM, sx, d);
                float ay = __shfl_up_sync(FULLM, sy, d);
                float az = __shfl_up_sync(FULLM, sz, d);
                float aw = __shfl_up_sync(FULLM, sw, d);
                if (lane >= d) { sx += ax; sy += ay; sz += az; sw += aw; }
            }
            float exx = __shfl_up_sync(FULLM, sx, 1);
            float exy = __shfl_up_sync(FULLM, sy, 1);
            float exz = __shfl_up_sync(FULLM, sz, 1);
            float exw = __shfl_up_sync(FULLM, sw, 1);
            if (lane == 0) { exx = exy = exz = exw = 0.f; }

            // Out-buffer reuse gate: store from 2 segs ago must be read-drained
            if (lane == 0)
                asm volatile("cp.async.bulk.wait_group.read 1;" ::: "memory");
            __syncwarp();

            char* ob = (char*)&s_out[wid][b][0];
            const float ox = bx + exx, oy = by + exy, oz = bz + exz, ow = bw + exw;
            #pragma unroll
            for (int k = 0; k < 4; ++k) {
                float4 o;
                o.x = ox + px[k]; o.y = oy + py[k];
                o.z = oz + pz[k]; o.w = ow + pw[k];
                *(float4*)(ob + swz16(4 * lane + k)) = o;
            }
            __syncwarp();
            if (lane == 0) {
                asm volatile("fence.proxy.async.shared::cta;" ::: "memory");
                tma_store_seg(&tmap_out, ybase + s * 16, b ? outb1 : outb0);
                asm volatile("cp.async.bulk.commit_group;" ::: "memory");
            }

            bx += __shfl_sync(FULLM, sx, 31);
            by += __shfl_sync(FULLM, sy, 31);
            bz += __shfl_sync(FULLM, sz, 31);
            bw += __shfl_sync(FULLM, sw, 31);
        }
    }
    if (lane == 0)
        asm volatile("cp.async.bulk.wait_group 0;" ::: "memory");
}

// ---------------- fallback kernel (proven R4, 131 us) ----------------
__global__ __launch_bounds__(TPB)
void socnet_fb(const float* __restrict__ X, const float* __restrict__ SC,
               const float* __restrict__ w_init1, const float* __restrict__ b_init1,
               const float* __restrict__ w_init2, const float* __restrict__ b_init2,
               const float* __restrict__ w_eta1,  const float* __restrict__ b_eta1,
               const float* __restrict__ w_eta2,  const float* __restrict__ b_eta2,
               float* __restrict__ out) {
    const int lane = threadIdx.x & 31;
    const int row  = blockIdx.x * WPC + (threadIdx.x >> 5);
    const float4* __restrict__ Xr = reinterpret_cast<const float4*>(X) + (size_t)row * L_LEN;
    float4* __restrict__ Or       = reinterpret_cast<float4*>(out)     + (size_t)row * L_LEN;
    const float Q = SC[row*4+0], eta0 = SC[row*4+1], R = SC[row*4+2], cap = SC[row*4+3];
    const float we0 = w_eta1[0], we1 = w_eta1[1], be1 = b_eta1[0];
    const float we2 = w_eta2[0], be2 = b_eta2[0];
    const float dscale = eta0 / (3600.0f * Q);
    float4 x0 = Xr[lane];
    float pI = x0.y, pT = x0.z, pU = x0.w;
    float pde = we2 * softplus_f(we0*pI + we1*pT + be1) + be2;
    const float I0 = __shfl_sync(FULLM, pI, 0);
    const float T0 = __shfl_sync(FULLM, pT, 0);
    const float U0 = __shfl_sync(FULLM, pU, 0);
    float z = w_init1[0]*I0 + w_init1[1]*T0 + w_init1[2]*U0 + w_init1[3]*R + b_init1[0];
    const float soc = cap * (1.0f + (w_init2[0]*softplus_f(z) + b_init2[0]));
    float bx = soc, by = soc, bz = soc, bw = soc;
    #pragma unroll 2
    for (int it = 0; it < L_LEN/32; ++it) {
        float nI, nT, nU, nde;
        if (it < L_LEN/32 - 1) {
            float4 xn = Xr[(it+1)*32 + lane];
            nI = xn.y; nT = xn.z; nU = xn.w;
            nde = we2 * softplus_f(we0*nI + we1*nT + be1) + be2;
        } else { nI = pI; nT = pT; nU = pU; nde = pde; }
        const int src = (lane + 1) & 31;
        const float qI  = __shfl_sync(FULLM, (lane==0)?nI :pI,  src);
        const float qT  = __shfl_sync(FULLM, (lane==0)?nT :pT,  src);
        const float qU  = __shfl_sync(FULLM, (lane==0)?nU :pU,  src);
        const float qde = __shfl_sync(FULLM, (lane==0)?nde:pde, src);
        const float dy = dscale * (1.0f + pde) * pI;
        float ex = dy*(qI-pI), ey = dy*(qT-pT), ez = dy*(qU-pU), ew = dy*(qde-pde);
        if (it == L_LEN/32 - 1 && lane == 31) { ex=ey=ez=ew=0.f; }
        float sx = ex, sy = ey, sz = ez, sw = ew;
        #pragma unroll
        for (int d = 1; d < 32; d <<= 1) {
            float ax = __shfl_up_sync(FULLM, sx, d);
            float ay = __shfl_up_sync(FULLM, sy, d);
            float az = __shfl_up_sync(FULLM, sz, d);
            float aw = __shfl_up_sync(FULLM, sw, d);
            if (lane >= d) { sx += ax; sy += ay; sz += az; sw += aw; }
        }
        float4 o;
        o.x = bx + (sx-ex); o.y = by + (sy-ey); o.z = bz + (sz-ez); o.w = bw + (sw-ew);
        Or[it*32 + lane] = o;
        bx += __shfl_sync(FULLM, sx, 31); by += __shfl_sync(FULLM, sy, 31);
        bz += __shfl_sync(FULLM, sz, 31); bw += __shfl_sync(FULLM, sw, 31);
        pI = nI; pT = nT; pU = nU; pde = nde;
    }
}

// ---------------- host ----------------
typedef CUresult (*PFN_encode)(CUtensorMap*, CUtensorMapDataType, cuuint32_t, void*,
                               const cuuint64_t*, const cuuint64_t*, const cuuint32_t*,
                               const cuuint32_t*, CUtensorMapInterleave, CUtensorMapSwizzle,
                               CUtensorMapL2promotion, CUtensorMapFloatOOBfill);

extern "C" void kernel_launch(void* const* d_in, const int* in_sizes, int n_in,
                              void* d_out, int out_size) {
    const float* X       = (const float*)d_in[0];
    const float* SC      = (const float*)d_in[1];
    const float* w_init1 = (const float*)d_in[2];
    const float* b_init1 = (const float*)d_in[3];
    const float* w_init2 = (const float*)d_in[4];
    const float* b_init2 = (const float*)d_in[5];
    const float* w_eta1  = (const float*)d_in[6];
    const float* b_eta1  = (const float*)d_in[7];
    const float* w_eta2  = (const float*)d_in[8];
    const float* b_eta2  = (const float*)d_in[9];
    float* out = (float*)d_out;

    void* fp = nullptr;
    cudaDriverEntryPointQueryResult qr;
    cudaGetDriverEntryPoint("cuTensorMapEncodeTiled", &fp,
                            cudaEnableDefault, &qr);

    bool tma_ok = false;
    CUtensorMap mIn, mOut;
    if (fp) {
        PFN_encode enc = (PFN_encode)fp;
        cuuint64_t dims[2]    = {32ull, (cuuint64_t)N_ROWS * ROW128};
        cuuint64_t strides[1] = {128ull};
        cuuint32_t box[2]     = {32u, 16u};
        cuuint32_t es[2]      = {1u, 1u};
        CUresult r1 = enc(&mIn, CU_TENSOR_MAP_DATA_TYPE_FLOAT32, 2, (void*)X,
                          dims, strides, box, es,
                          CU_TENSOR_MAP_INTERLEAVE_NONE, CU_TENSOR_MAP_SWIZZLE_128B,
                          CU_TENSOR_MAP_L2_PROMOTION_L2_128B,
                          CU_TENSOR_MAP_FLOAT_OOB_FILL_NONE);
        CUresult r2 = enc(&mOut, CU_TENSOR_MAP_DATA_TYPE_FLOAT32, 2, (void*)out,
                          dims, strides, box, es,
                          CU_TENSOR_MAP_INTERLEAVE_NONE, CU_TENSOR_MAP_SWIZZLE_128B,
                          CU_TENSOR_MAP_L2_PROMOTION_L2_128B,
                          CU_TENSOR_MAP_FLOAT_OOB_FILL_NONE);
        tma_ok = (r1 == CUDA_SUCCESS && r2 == CUDA_SUCCESS);
    }

    if (tma_ok) {
        socnet_tma<<<GRID, TPB>>>(mIn, mOut, SC,
                                  w_init1, b_init1, w_init2, b_init2,
                                  w_eta1, b_eta1, w_eta2, b_eta2);
    } else {
        socnet_fb<<<GRID, TPB>>>(X, SC,
                                 w_init1, b_init1, w_init2, b_init2,
                                 w_eta1, b_eta1, w_eta2, b_eta2, out);
    }
}

// round 7
// speedup vs baseline: 1.3293x; 1.0814x over previous
#include <cuda_runtime.h>
#include <cuda.h>
#include <cstdint>

#define L_LEN     4096
#define N_ROWS    4096
#define TPB       64                 // 2 warps per CTA, one row per warp
#define WPC       2
#define GRID      (N_ROWS / WPC)     // 2048 CTAs
#define SEGS      16                 // 4KB segments per row
#define SEG_F4    256                // float4 per segment
#define SEG_BYTES 4096
#define YSTEP     32                 // 128B-rows per segment
#define ROWY      512                // 128B-rows per data row
#define EPT       8                  // consecutive elements per thread
#define FULLM     0xFFFFFFFFu

// Fast, numerically safe softplus: max(x,0) + log(1 + e^{-|x|})
__device__ __forceinline__ float softplus_f(float x) {
    return fmaxf(x, 0.0f) + __logf(1.0f + __expf(-fabsf(x)));
}

// SW128 swizzled byte offset of float4 element e within a 4KB tile (128B rows)
__device__ __forceinline__ int swz16(int e) {
    int b = e << 4;
    return b ^ ((b >> 3) & 0x70);
}

__device__ __forceinline__ uint32_t smem_u32(const void* p) {
    return (uint32_t)__cvta_generic_to_shared(p);
}
__device__ __forceinline__ void mbar_init(uint32_t a, uint32_t cnt) {
    asm volatile("mbarrier.init.shared.b64 [%0], %1;" :: "r"(a), "r"(cnt) : "memory");
}
__device__ __forceinline__ void mbar_expect_tx(uint32_t a, uint32_t bytes) {
    asm volatile("mbarrier.arrive.expect_tx.shared.b64 _, [%0], %1;"
                 :: "r"(a), "r"(bytes) : "memory");
}
__device__ __forceinline__ void mbar_wait(uint32_t a, uint32_t parity) {
    asm volatile(
        "{\n\t.reg .pred P;\n\t"
        "W_%=:\n\t"
        "mbarrier.try_wait.parity.acquire.cta.shared::cta.b64 P, [%0], %1;\n\t"
        "@!P bra W_%=;\n\t}"
        :: "r"(a), "r"(parity) : "memory");
}
__device__ __forceinline__ void tma_load_seg(uint32_t dst, const CUtensorMap* m,
                                             int y, uint32_t mbar) {
    asm volatile("cp.async.bulk.tensor.2d.shared::cta.global.tile.mbarrier::complete_tx::bytes "
                 "[%0], [%1, {%2, %3}], [%4];"
                 :: "r"(dst), "l"(m), "r"(0), "r"(y), "r"(mbar) : "memory");
}
__device__ __forceinline__ void tma_store_seg(const CUtensorMap* m, int y, uint32_t src) {
    asm volatile("cp.async.bulk.tensor.2d.global.shared::cta.tile.bulk_group "
                 "[%0, {%1, %2}], [%3];"
                 :: "l"(m), "r"(0), "r"(y), "r"(src) : "memory");
}

__global__ __launch_bounds__(TPB)
void socnet_tma(const __grid_constant__ CUtensorMap tmap_in,
                const __grid_constant__ CUtensorMap tmap_out,
                const float* __restrict__ SC,
                const float* __restrict__ w_init1, const float* __restrict__ b_init1,
                const float* __restrict__ w_init2, const float* __restrict__ b_init2,
                const float* __restrict__ w_eta1,  const float* __restrict__ b_eta1,
                const float* __restrict__ w_eta2,  const float* __restrict__ b_eta2) {
    __shared__ __align__(1024) float4 s_in [WPC][2][SEG_F4];   // 2 x 4KB per warp
    __shared__ __align__(1024) float4 s_out[WPC][SEG_F4];      // 1 x 4KB per warp
    __shared__ unsigned long long     s_mbar[WPC][2];

    const int lane = threadIdx.x & 31;
    const int wid  = threadIdx.x >> 5;
    const int row  = blockIdx.x * WPC + wid;
    const int ybase = row * ROWY;

    const float we0 = w_eta1[0], we1 = w_eta1[1], be1 = b_eta1[0];
    const float we2 = w_eta2[0], be2 = b_eta2[0];

    const uint32_t mb0  = smem_u32(&s_mbar[wid][0]);
    const uint32_t mb1  = smem_u32(&s_mbar[wid][1]);
    const uint32_t inb0 = smem_u32(&s_in[wid][0][0]);
    const uint32_t inb1 = smem_u32(&s_in[wid][1][0]);
    const uint32_t outb = smem_u32(&s_out[wid][0]);

    if (lane == 0) { mbar_init(mb0, 1); mbar_init(mb1, 1); }
    asm volatile("fence.proxy.async.shared::cta;" ::: "memory");
    __syncwarp();

    if (lane == 0) {
        mbar_expect_tx(mb0, SEG_BYTES);
        tma_load_seg(inb0, &tmap_in, ybase, mb0);
        mbar_expect_tx(mb1, SEG_BYTES);
        tma_load_seg(inb1, &tmap_in, ybase + YSTEP, mb1);
    }
    uint32_t ph0 = 0, ph1 = 0;
    mbar_wait(mb0, 0); ph0 = 1;                      // seg 0 ready

    // Per-row scalars: SC = [Q, eta0, R, cap]; soc_init from element 0
    const float Q    = SC[row * 4 + 0];
    const float eta0 = SC[row * 4 + 1];
    const float R    = SC[row * 4 + 2];
    const float cap  = SC[row * 4 + 3];
    const float dscale = eta0 / (3600.0f * Q);

    float4 x0 = s_in[wid][0][0];                     // swz16(0)==0, broadcast
    float z = w_init1[0] * x0.y + w_init1[1] * x0.z
            + w_init1[2] * x0.w + w_init1[3] * R + b_init1[0];
    const float soc = cap * (1.0f + (w_init2[0] * softplus_f(z) + b_init2[0]));
    float bx = soc, by = soc, bz = soc, bw = soc;

    // Per-thread swizzled byte base of its 128B row within a tile
    const int rbase = lane << 7;                     // lane*128
    const int cswz  = (lane & 7) << 4;               // XOR pattern for columns

    #pragma unroll 1
    for (int s = 0; s < SEGS; ++s) {
        const int b = s & 1;
        const char* ib  = (const char*)&s_in[wid][b][0];
        const char* ibN = (const char*)&s_in[wid][b ^ 1][0];

        if (s < SEGS - 1) {                          // wait seg s+1 (boundary source)
            if (b) { mbar_wait(mb0, ph0); ph0 ^= 1; }
            else   { mbar_wait(mb1, ph1); ph1 ^= 1; }
        }

        // Own 8 consecutive elements = this lane's 128B row (conflict-free)
        float I[EPT], T[EPT], U[EPT], de[EPT];
        #pragma unroll
        for (int k = 0; k < EPT; ++k) {
            float4 x = *(const float4*)(ib + (rbase | ((k << 4) ^ cswz)));
            I[k] = x.y; T[k] = x.z; U[k] = x.w;
            de[k] = we2 * softplus_f(we0 * I[k] + we1 * T[k] + be1) + be2;
        }
        // Boundary = elem 0 of seg s+1 (stale/unused for final seg)
        float4 bnd = *(const float4*)(ibN);
        const float bde = we2 * softplus_f(we0 * bnd.y + we1 * bnd.z + be1) + be2;

        float nI  = __shfl_down_sync(FULLM, I[0], 1);
        float nT  = __shfl_down_sync(FULLM, T[0], 1);
        float nU  = __shfl_down_sync(FULLM, U[0], 1);
        float nde = __shfl_down_sync(FULLM, de[0], 1);
        if (lane == 31) { nI = bnd.y; nT = bnd.z; nU = bnd.w; nde = bde; }

        // Serial local exclusive prefixes; zero the nonexistent inc[L-1]
        const float lastmask = (s == SEGS - 1 && lane == 31) ? 0.0f : 1.0f;
        float px[EPT], py[EPT], pz[EPT], pw[EPT];
        float tx = 0.f, ty = 0.f, tz = 0.f, tw = 0.f;
        #pragma unroll
        for (int k = 0; k < EPT; ++k) {
            px[k] = tx; py[k] = ty; pz[k] = tz; pw[k] = tw;
            const float xI = (k < EPT - 1) ? I[k + 1]  : nI;
            const float xT = (k < EPT - 1) ? T[k + 1]  : nT;
            const float xU = (k < EPT - 1) ? U[k + 1]  : nU;
            const float xd = (k < EPT - 1) ? de[k + 1] : nde;
            float dy = dscale * (1.0f + de[k]) * I[k];
            if (k == EPT - 1) dy *= lastmask;
            tx += dy * (xI - I[k]);
            ty += dy * (xT - T[k]);
            tz += dy * (xU - U[k]);
            tw += dy * (xd - de[k]);
        }

        // Inputs consumed -> refill this in-buffer with seg s+2
        __syncwarp();
        if (s + 2 < SEGS && lane == 0) {
            if (b) { mbar_expect_tx(mb1, SEG_BYTES);
                     tma_load_seg(inb1, &tmap_in, ybase + (s + 2) * YSTEP, mb1); }
            else   { mbar_expect_tx(mb0, SEG_BYTES);
                     tma_load_seg(inb0, &tmap_in, ybase + (s + 2) * YSTEP, mb0); }
        }

        // Warp scan of thread totals (once per 256 elements)
        float sx = tx, sy = ty, sz = tz, sw = tw;
        #pragma unroll
        for (int d = 1; d < 32; d <<= 1) {
            float ax = __shfl_up_sync(FULLM, sx, d);
            float ay = __shfl_up_sync(FULLM, sy, d);
            float az = __shfl_up_sync(FULLM, sz, d);
            float aw = __shfl_up_sync(FULLM, sw, d);
            if (lane >= d) { sx += ax; sy += ay; sz += az; sw += aw; }
        }
        float exx = __shfl_up_sync(FULLM, sx, 1);
        float exy = __shfl_up_sync(FULLM, sy, 1);
        float exz = __shfl_up_sync(FULLM, sz, 1);
        float exw = __shfl_up_sync(FULLM, sw, 1);
        if (lane == 0) { exx = exy = exz = exw = 0.f; }

        // Single out-buffer: previous store must be fully read-drained
        if (lane == 0)
            asm volatile("cp.async.bulk.wait_group.read 0;" ::: "memory");
        __syncwarp();

        char* ob = (char*)&s_out[wid][0];
        const float ox = bx + exx, oy = by + exy, oz = bz + exz, ow = bw + exw;
        #pragma unroll
        for (int k = 0; k < EPT; ++k) {
            float4 o;
            o.x = ox + px[k]; o.y = oy + py[k];
            o.z = oz + pz[k]; o.w = ow + pw[k];
            *(float4*)(ob + (rbase | ((k << 4) ^ cswz))) = o;
        }
        __syncwarp();
        if (lane == 0) {
            asm volatile("fence.proxy.async.shared::cta;" ::: "memory");
            tma_store_seg(&tmap_out, ybase + s * YSTEP, outb);
            asm volatile("cp.async.bulk.commit_group;" ::: "memory");
        }

        bx += __shfl_sync(FULLM, sx, 31);
        by += __shfl_sync(FULLM, sy, 31);
        bz += __shfl_sync(FULLM, sz, 31);
        bw += __shfl_sync(FULLM, sw, 31);
    }

    if (lane == 0)
        asm volatile("cp.async.bulk.wait_group 0;" ::: "memory");
}

// ---------------- fallback kernel (proven R4 warp-scan, 131 us) ----------------
__global__ __launch_bounds__(128)
void socnet_fb(const float* __restrict__ X, const float* __restrict__ SC,
               const float* __restrict__ w_init1, const float* __restrict__ b_init1,
               const float* __restrict__ w_init2, const float* __restrict__ b_init2,
               const float* __restrict__ w_eta1,  const float* __restrict__ b_eta1,
               const float* __restrict__ w_eta2,  const float* __restrict__ b_eta2,
               float* __restrict__ out) {
    const int lane = threadIdx.x & 31;
    const int row  = blockIdx.x * 4 + (threadIdx.x >> 5);
    const float4* __restrict__ Xr = reinterpret_cast<const float4*>(X) + (size_t)row * L_LEN;
    float4* __restrict__ Or       = reinterpret_cast<float4*>(out)     + (size_t)row * L_LEN;
    const float Q = SC[row*4+0], eta0 = SC[row*4+1], R = SC[row*4+2], cap = SC[row*4+3];
    const float we0 = w_eta1[0], we1 = w_eta1[1], be1 = b_eta1[0];
    const float we2 = w_eta2[0], be2 = b_eta2[0];
    const float dscale = eta0 / (3600.0f * Q);
    float4 x0 = Xr[lane];
    float pI = x0.y, pT = x0.z, pU = x0.w;
    float pde = we2 * softplus_f(we0*pI + we1*pT + be1) + be2;
    const float I0 = __shfl_sync(FULLM, pI, 0);
    const float T0 = __shfl_sync(FULLM, pT, 0);
    const float U0 = __shfl_sync(FULLM, pU, 0);
    float z = w_init1[0]*I0 + w_init1[1]*T0 + w_init1[2]*U0 + w_init1[3]*R + b_init1[0];
    const float soc = cap * (1.0f + (w_init2[0]*softplus_f(z) + b_init2[0]));
    float bx = soc, by = soc, bz = soc, bw = soc;
    #pragma unroll 2
    for (int it = 0; it < L_LEN/32; ++it) {
        float nI, nT, nU, nde;
        if (it < L_LEN/32 - 1) {
            float4 xn = Xr[(it+1)*32 + lane];
            nI = xn.y; nT = xn.z; nU = xn.w;
            nde = we2 * softplus_f(we0*nI + we1*nT + be1) + be2;
        } else { nI = pI; nT = pT; nU = pU; nde = pde; }
        const int src = (lane + 1) & 31;
        const float qI  = __shfl_sync(FULLM, (lane==0)?nI :pI,  src);
        const float qT  = __shfl_sync(FULLM, (lane==0)?nT :pT,  src);
        const float qU  = __shfl_sync(FULLM, (lane==0)?nU :pU,  src);
        const float qde = __shfl_sync(FULLM, (lane==0)?nde:pde, src);
        const float dy = dscale * (1.0f + pde) * pI;
        float ex = dy*(qI-pI), ey = dy*(qT-pT), ez = dy*(qU-pU), ew = dy*(qde-pde);
        if (it == L_LEN/32 - 1 && lane == 31) { ex=ey=ez=ew=0.f; }
        float sx = ex, sy = ey, sz = ez, sw = ew;
        #pragma unroll
        for (int d = 1; d < 32; d <<= 1) {
            float ax = __shfl_up_sync(FULLM, sx, d);
            float ay = __shfl_up_sync(FULLM, sy, d);
            float az = __shfl_up_sync(FULLM, sz, d);
            float aw = __shfl_up_sync(FULLM, sw, d);
            if (lane >= d) { sx += ax; sy += ay; sz += az; sw += aw; }
        }
        float4 o;
        o.x = bx + (sx-ex); o.y = by + (sy-ey); o.z = bz + (sz-ez); o.w = bw + (sw-ew);
        Or[it*32 + lane] = o;
        bx += __shfl_sync(FULLM, sx, 31); by += __shfl_sync(FULLM, sy, 31);
        bz += __shfl_sync(FULLM, sz, 31); bw += __shfl_sync(FULLM, sw, 31);
        pI = nI; pT = nT; pU = nU; pde = nde;
    }
}

// ---------------- host ----------------
typedef CUresult (*PFN_encode)(CUtensorMap*, CUtensorMapDataType, cuuint32_t, void*,
                               const cuuint64_t*, const cuuint64_t*, const cuuint32_t*,
                               const cuuint32_t*, CUtensorMapInterleave, CUtensorMapSwizzle,
                               CUtensorMapL2promotion, CUtensorMapFloatOOBfill);

extern "C" void kernel_launch(void* const* d_in, const int* in_sizes, int n_in,
                              void* d_out, int out_size) {
    const float* X       = (const float*)d_in[0];
    const float* SC      = (const float*)d_in[1];
    const float* w_init1 = (const float*)d_in[2];
    const float* b_init1 = (const float*)d_in[3];
    const float* w_init2 = (const float*)d_in[4];
    const float* b_init2 = (const float*)d_in[5];
    const float* w_eta1  = (const float*)d_in[6];
    const float* b_eta1  = (const float*)d_in[7];
    const float* w_eta2  = (const float*)d_in[8];
    const float* b_eta2  = (const float*)d_in[9];
    float* out = (float*)d_out;

    void* fp = nullptr;
    cudaDriverEntryPointQueryResult qr;
    cudaGetDriverEntryPoint("cuTensorMapEncodeTiled", &fp,
                            cudaEnableDefault, &qr);

    bool tma_ok = false;
    CUtensorMap mIn, mOut;
    if (fp) {
        PFN_encode enc = (PFN_encode)fp;
        cuuint64_t dims[2]    = {32ull, (cuuint64_t)N_ROWS * ROWY};
        cuuint64_t strides[1] = {128ull};
        cuuint32_t box[2]     = {32u, 32u};       // 4KB tile
        cuuint32_t es[2]      = {1u, 1u};
        CUresult r1 = enc(&mIn, CU_TENSOR_MAP_DATA_TYPE_FLOAT32, 2, (void*)X,
                          dims, strides, box, es,
                          CU_TENSOR_MAP_INTERLEAVE_NONE, CU_TENSOR_MAP_SWIZZLE_128B,
                          CU_TENSOR_MAP_L2_PROMOTION_L2_128B,
                          CU_TENSOR_MAP_FLOAT_OOB_FILL_NONE);
        CUresult r2 = enc(&mOut, CU_TENSOR_MAP_DATA_TYPE_FLOAT32, 2, (void*)out,
                          dims, strides, box, es,
                          CU_TENSOR_MAP_INTERLEAVE_NONE, CU_TENSOR_MAP_SWIZZLE_128B,
                          CU_TENSOR_MAP_L2_PROMOTION_L2_128B,
                          CU_TENSOR_MAP_FLOAT_OOB_FILL_NONE);
        tma_ok = (r1 == CUDA_SUCCESS && r2 == CUDA_SUCCESS);
    }

    if (tma_ok) {
        socnet_tma<<<GRID, TPB>>>(mIn, mOut, SC,
                                  w_init1, b_init1, w_init2, b_init2,
                                  w_eta1, b_eta1, w_eta2, b_eta2);
    } else {
        socnet_fb<<<N_ROWS / 4, 128>>>(X, SC,
                                       w_init1, b_init1, w_init2, b_init2,
                                       w_eta1, b_eta1, w_eta2, b_eta2, out);
    }
}

// round 8
// speedup vs baseline: 1.3916x; 1.0469x over previous
#include <cuda_runtime.h>
#include <cuda.h>
#include <cstdint>

#define L_LEN     4096
#define N_ROWS    4096
#define TPB       64                 // 2 warps per CTA, one row per warp
#define WPC       2
#define GRID      (N_ROWS / WPC)     // 2048 CTAs
#define SEGS      16                 // 4KB segments per row
#define SEG_F4    256                // float4 per segment
#define SEG_BYTES 4096
#define YSTEP     32                 // 128B-rows per segment
#define ROWY      512                // 128B-rows per data row
#define EPT       8                  // consecutive elements per thread
#define FULLM     0xFFFFFFFFu

// Fast, numerically safe softplus: max(x,0) + log(1 + e^{-|x|})
__device__ __forceinline__ float softplus_f(float x) {
    return fmaxf(x, 0.0f) + __logf(1.0f + __expf(-fabsf(x)));
}

__device__ __forceinline__ uint32_t smem_u32(const void* p) {
    return (uint32_t)__cvta_generic_to_shared(p);
}
__device__ __forceinline__ void mbar_init(uint32_t a, uint32_t cnt) {
    asm volatile("mbarrier.init.shared.b64 [%0], %1;" :: "r"(a), "r"(cnt) : "memory");
}
__device__ __forceinline__ void mbar_expect_tx(uint32_t a, uint32_t bytes) {
    asm volatile("mbarrier.arrive.expect_tx.shared.b64 _, [%0], %1;"
                 :: "r"(a), "r"(bytes) : "memory");
}
__device__ __forceinline__ void mbar_wait(uint32_t a, uint32_t parity) {
    asm volatile(
        "{\n\t.reg .pred P;\n\t"
        "W_%=:\n\t"
        "mbarrier.try_wait.parity.acquire.cta.shared::cta.b64 P, [%0], %1;\n\t"
        "@!P bra W_%=;\n\t}"
        :: "r"(a), "r"(parity) : "memory");
}
__device__ __forceinline__ void tma_load_seg(uint32_t dst, const CUtensorMap* m,
                                             int y, uint32_t mbar) {
    asm volatile("cp.async.bulk.tensor.2d.shared::cta.global.tile.mbarrier::complete_tx::bytes "
                 "[%0], [%1, {%2, %3}], [%4];"
                 :: "r"(dst), "l"(m), "r"(0), "r"(y), "r"(mbar) : "memory");
}
__device__ __forceinline__ void tma_store_seg(const CUtensorMap* m, int y, uint32_t src) {
    asm volatile("cp.async.bulk.tensor.2d.global.shared::cta.tile.bulk_group "
                 "[%0, {%1, %2}], [%3];"
                 :: "l"(m), "r"(0), "r"(y), "r"(src) : "memory");
}

__global__ __launch_bounds__(TPB)
void socnet_tma(const __grid_constant__ CUtensorMap tmap_in,
                const __grid_constant__ CUtensorMap tmap_out,
                const float* __restrict__ X,
                const float* __restrict__ SC,
                const float* __restrict__ w_init1, const float* __restrict__ b_init1,
                const float* __restrict__ w_init2, const float* __restrict__ b_init2,
                const float* __restrict__ w_eta1,  const float* __restrict__ b_eta1,
                const float* __restrict__ w_eta2,  const float* __restrict__ b_eta2) {
    __shared__ __align__(1024) float4 s_in [WPC][2][SEG_F4];   // 2 x 4KB per warp
    __shared__ __align__(1024) float4 s_out[WPC][2][SEG_F4];   // 2 x 4KB per warp
    __shared__ unsigned long long     s_mbar[WPC][2];

    const int lane = threadIdx.x & 31;
    const int wid  = threadIdx.x >> 5;
    const int row  = blockIdx.x * WPC + wid;
    const int ybase = row * ROWY;

    const float we0 = w_eta1[0], we1 = w_eta1[1], be1 = b_eta1[0];
    const float we2 = w_eta2[0], be2 = b_eta2[0];

    const uint32_t mb0  = smem_u32(&s_mbar[wid][0]);
    const uint32_t mb1  = smem_u32(&s_mbar[wid][1]);
    const uint32_t inb0 = smem_u32(&s_in[wid][0][0]);
    const uint32_t inb1 = smem_u32(&s_in[wid][1][0]);
    const uint32_t oub0 = smem_u32(&s_out[wid][0][0]);
    const uint32_t oub1 = smem_u32(&s_out[wid][1][0]);

    if (lane == 0) { mbar_init(mb0, 1); mbar_init(mb1, 1); }
    asm volatile("fence.proxy.async.shared::cta;" ::: "memory");
    __syncwarp();

    if (lane == 0) {
        mbar_expect_tx(mb0, SEG_BYTES);
        tma_load_seg(inb0, &tmap_in, ybase, mb0);
        mbar_expect_tx(mb1, SEG_BYTES);
        tma_load_seg(inb1, &tmap_in, ybase + YSTEP, mb1);
    }
    uint32_t ph0 = 0, ph1 = 0;

    // Per-row scalars: SC = [Q, eta0, R, cap]
    const float Q    = SC[row * 4 + 0];
    const float eta0 = SC[row * 4 + 1];
    const float R    = SC[row * 4 + 2];
    const float cap  = SC[row * 4 + 3];
    const float dscale = eta0 / (3600.0f * Q);

    const float4* __restrict__ Xg = reinterpret_cast<const float4*>(X) + (size_t)row * L_LEN;

    mbar_wait(mb0, 0); ph0 = 1;                      // seg 0 ready

    // soc_init from element 0 (swizzle(0)==0, broadcast LDS)
    float4 x0 = s_in[wid][0][0];
    float z = w_init1[0] * x0.y + w_init1[1] * x0.z
            + w_init1[2] * x0.w + w_init1[3] * R + b_init1[0];
    const float soc = cap * (1.0f + (w_init2[0] * softplus_f(z) + b_init2[0]));
    float bx = soc, by = soc, bz = soc, bw = soc;

    // Per-thread swizzled byte base of its 128B row within a 4KB tile
    const int rbase = lane << 7;                     // lane*128
    const int cswz  = (lane & 7) << 4;               // XOR pattern for columns

    #pragma unroll 1
    for (int s = 0; s < SEGS; ++s) {
        const int b = s & 1;
        const char* ib = (const char*)&s_in[wid][b][0];

        // Boundary element (first elem of seg s+1) via global LDG, lane 31
        // only; issued before the wait so latency overlaps. For the final
        // segment clamp in-bounds (value masked later).
        float4 bnd;
        const int bidx = (s + 1 < SEGS) ? (s + 1) * SEG_F4 : (L_LEN - 1);
        if (lane == 31) bnd = __ldg(&Xg[bidx]);

        if (s > 0) {                                 // wait own seg
            if (b) { mbar_wait(mb1, ph1); ph1 ^= 1; }
            else   { mbar_wait(mb0, ph0); ph0 ^= 1; }
        }

        // First element of this lane's 8; save for the shfl handoff
        float4 xc = *(const float4*)(ib + (rbase | cswz));   // k=0: (0<<4)^cswz
        float cI = xc.y, cT = xc.z, cU = xc.w;
        float cde = we2 * softplus_f(we0 * cI + we1 * cT + be1) + be2;

        // Neighbor of this lane's last element = next lane's first element
        float nI  = __shfl_down_sync(FULLM, cI, 1);
        float nT  = __shfl_down_sync(FULLM, cT, 1);
        float nU  = __shfl_down_sync(FULLM, cU, 1);
        float nde = __shfl_down_sync(FULLM, cde, 1);
        if (lane == 31) {
            nI = bnd.y; nT = bnd.z; nU = bnd.w;
            nde = we2 * softplus_f(we0 * nI + we1 * nT + be1) + be2;
        }

        // Serial local exclusive prefixes; zero the nonexistent inc[L-1]
        const float lastmask = (s == SEGS - 1 && lane == 31) ? 0.0f : 1.0f;
        float px[EPT], py[EPT], pz[EPT], pw[EPT];
        float tx = 0.f, ty = 0.f, tz = 0.f, tw = 0.f;
        #pragma unroll
        for (int k = 0; k < EPT; ++k) {
            px[k] = tx; py[k] = ty; pz[k] = tz; pw[k] = tw;
            float xI, xT, xU, xd;
            if (k < EPT - 1) {
                float4 xn = *(const float4*)(ib + (rbase | (((k + 1) << 4) ^ cswz)));
                xI = xn.y; xT = xn.z; xU = xn.w;
                xd = we2 * softplus_f(we0 * xI + we1 * xT + be1) + be2;
            } else {
                xI = nI; xT = nT; xU = nU; xd = nde;
            }
            float dy = dscale * (1.0f + cde) * cI;
            if (k == EPT - 1) dy *= lastmask;
            tx += dy * (xI - cI);
            ty += dy * (xT - cT);
            tz += dy * (xU - cU);
            tw += dy * (xd - cde);
            cI = xI; cT = xT; cU = xU; cde = xd;
        }

        // Inputs consumed -> refill this in-buffer with seg s+2
        __syncwarp();
        if (s + 2 < SEGS && lane == 0) {
            if (b) { mbar_expect_tx(mb1, SEG_BYTES);
                     tma_load_seg(inb1, &tmap_in, ybase + (s + 2) * YSTEP, mb1); }
            else   { mbar_expect_tx(mb0, SEG_BYTES);
                     tma_load_seg(inb0, &tmap_in, ybase + (s + 2) * YSTEP, mb0); }
        }

        // Warp scan of thread totals (once per 256 elements)
        float sx = tx, sy = ty, sz = tz, sw = tw;
        #pragma unroll
        for (int d = 1; d < 32; d <<= 1) {
            float ax = __shfl_up_sync(FULLM, sx, d);
            float ay = __shfl_up_sync(FULLM, sy, d);
            float az = __shfl_up_sync(FULLM, sz, d);
            float aw = __shfl_up_sync(FULLM, sw, d);
            if (lane >= d) { sx += ax; sy += ay; sz += az; sw += aw; }
        }
        float exx = __shfl_up_sync(FULLM, sx, 1);
        float exy = __shfl_up_sync(FULLM, sy, 1);
        float exz = __shfl_up_sync(FULLM, sz, 1);
        float exw = __shfl_up_sync(FULLM, sw, 1);
        if (lane == 0) { exx = exy = exz = exw = 0.f; }

        // Double-buffered out: the store issued 2 segs ago must be drained
        if (lane == 0)
            asm volatile("cp.async.bulk.wait_group.read 1;" ::: "memory");
        __syncwarp();

        char* ob = (char*)&s_out[wid][b][0];
        const float ox = bx + exx, oy = by + exy, oz = bz + exz, ow = bw + exw;
        #pragma unroll
        for (int k = 0; k < EPT; ++k) {
            float4 o;
            o.x = ox + px[k]; o.y = oy + py[k];
            o.z = oz + pz[k]; o.w = ow + pw[k];
            *(float4*)(ob + (rbase | ((k << 4) ^ cswz))) = o;
        }
        __syncwarp();
        if (lane == 0) {
            asm volatile("fence.proxy.async.shared::cta;" ::: "memory");
            tma_store_seg(&tmap_out, ybase + s * YSTEP, b ? oub1 : oub0);
            asm volatile("cp.async.bulk.commit_group;" ::: "memory");
        }

        bx += __shfl_sync(FULLM, sx, 31);
        by += __shfl_sync(FULLM, sy, 31);
        bz += __shfl_sync(FULLM, sz, 31);
        bw += __shfl_sync(FULLM, sw, 31);
    }

    if (lane == 0)
        asm volatile("cp.async.bulk.wait_group 0;" ::: "memory");
}

// ---------------- fallback kernel (proven R4 warp-scan, 131 us) ----------------
__global__ __launch_bounds__(128)
void socnet_fb(const float* __restrict__ X, const float* __restrict__ SC,
               const float* __restrict__ w_init1, const float* __restrict__ b_init1,
               const float* __restrict__ w_init2, const float* __restrict__ b_init2,
               const float* __restrict__ w_eta1,  const float* __restrict__ b_eta1,
               const float* __restrict__ w_eta2,  const float* __restrict__ b_eta2,
               float* __restrict__ out) {
    const int lane = threadIdx.x & 31;
    const int row  = blockIdx.x * 4 + (threadIdx.x >> 5);
    const float4* __restrict__ Xr = reinterpret_cast<const float4*>(X) + (size_t)row * L_LEN;
    float4* __restrict__ Or       = reinterpret_cast<float4*>(out)     + (size_t)row * L_LEN;
    const float Q = SC[row*4+0], eta0 = SC[row*4+1], R = SC[row*4+2], cap = SC[row*4+3];
    const float we0 = w_eta1[0], we1 = w_eta1[1], be1 = b_eta1[0];
    const float we2 = w_eta2[0], be2 = b_eta2[0];
    const float dscale = eta0 / (3600.0f * Q);
    float4 x0 = Xr[lane];
    float pI = x0.y, pT = x0.z, pU = x0.w;
    float pde = we2 * softplus_f(we0*pI + we1*pT + be1) + be2;
    const float I0 = __shfl_sync(FULLM, pI, 0);
    const float T0 = __shfl_sync(FULLM, pT, 0);
    const float U0 = __shfl_sync(FULLM, pU, 0);
    float z = w_init1[0]*I0 + w_init1[1]*T0 + w_init1[2]*U0 + w_init1[3]*R + b_init1[0];
    const float soc = cap * (1.0f + (w_init2[0]*softplus_f(z) + b_init2[0]));
    float bx = soc, by = soc, bz = soc, bw = soc;
    #pragma unroll 2
    for (int it = 0; it < L_LEN/32; ++it) {
        float nI, nT, nU, nde;
        if (it < L_LEN/32 - 1) {
            float4 xn = Xr[(it+1)*32 + lane];
            nI = xn.y; nT = xn.z; nU = xn.w;
            nde = we2 * softplus_f(we0*nI + we1*nT + be1) + be2;
        } else { nI = pI; nT = pT; nU = pU; nde = pde; }
        const int src = (lane + 1) & 31;
        const float qI  = __shfl_sync(FULLM, (lane==0)?nI :pI,  src);
        const float qT  = __shfl_sync(FULLM, (lane==0)?nT :pT,  src);
        const float qU  = __shfl_sync(FULLM, (lane==0)?nU :pU,  src);
        const float qde = __shfl_sync(FULLM, (lane==0)?nde:pde, src);
        const float dy = dscale * (1.0f + pde) * pI;
        float ex = dy*(qI-pI), ey = dy*(qT-pT), ez = dy*(qU-pU), ew = dy*(qde-pde);
        if (it == L_LEN/32 - 1 && lane == 31) { ex=ey=ez=ew=0.f; }
        float sx = ex, sy = ey, sz = ez, sw = ew;
        #pragma unroll
        for (int d = 1; d < 32; d <<= 1) {
            float ax = __shfl_up_sync(FULLM, sx, d);
            float ay = __shfl_up_sync(FULLM, sy, d);
            float az = __shfl_up_sync(FULLM, sz, d);
            float aw = __shfl_up_sync(FULLM, sw, d);
            if (lane >= d) { sx += ax; sy += ay; sz += az; sw += aw; }
        }
        float4 o;
        o.x = bx + (sx-ex); o.y = by + (sy-ey); o.z = bz + (sz-ez); o.w = bw + (sw-ew);
        Or[it*32 + lane] = o;
        bx += __shfl_sync(FULLM, sx, 31); by += __shfl_sync(FULLM, sy, 31);
        bz += __shfl_sync(FULLM, sz, 31); bw += __shfl_sync(FULLM, sw, 31);
        pI = nI; pT = nT; pU = nU; pde = nde;
    }
}

// ---------------- host ----------------
typedef CUresult (*PFN_encode)(CUtensorMap*, CUtensorMapDataType, cuuint32_t, void*,
                               const cuuint64_t*, const cuuint64_t*, const cuuint32_t*,
                               const cuuint32_t*, CUtensorMapInterleave, CUtensorMapSwizzle,
                               CUtensorMapL2promotion, CUtensorMapFloatOOBfill);

extern "C" void kernel_launch(void* const* d_in, const int* in_sizes, int n_in,
                              void* d_out, int out_size) {
    const float* X       = (const float*)d_in[0];
    const float* SC      = (const float*)d_in[1];
    const float* w_init1 = (const float*)d_in[2];
    const float* b_init1 = (const float*)d_in[3];
    const float* w_init2 = (const float*)d_in[4];
    const float* b_init2 = (const float*)d_in[5];
    const float* w_eta1  = (const float*)d_in[6];
    const float* b_eta1  = (const float*)d_in[7];
    const float* w_eta2  = (const float*)d_in[8];
    const float* b_eta2  = (const float*)d_in[9];
    float* out = (float*)d_out;

    void* fp = nullptr;
    cudaDriverEntryPointQueryResult qr;
    cudaGetDriverEntryPoint("cuTensorMapEncodeTiled", &fp,
                            cudaEnableDefault, &qr);

    bool tma_ok = false;
    CUtensorMap mIn, mOut;
    if (fp) {
        PFN_encode enc = (PFN_encode)fp;
        cuuint64_t dims[2]    = {32ull, (cuuint64_t)N_ROWS * ROWY};
        cuuint64_t strides[1] = {128ull};
        cuuint32_t box[2]     = {32u, 32u};       // 4KB tile
        cuuint32_t es[2]      = {1u, 1u};
        CUresult r1 = enc(&mIn, CU_TENSOR_MAP_DATA_TYPE_FLOAT32, 2, (void*)X,
                          dims, strides, box, es,
                          CU_TENSOR_MAP_INTERLEAVE_NONE, CU_TENSOR_MAP_SWIZZLE_128B,
                          CU_TENSOR_MAP_L2_PROMOTION_L2_128B,
                          CU_TENSOR_MAP_FLOAT_OOB_FILL_NONE);
        CUresult r2 = enc(&mOut, CU_TENSOR_MAP_DATA_TYPE_FLOAT32, 2, (void*)out,
                          dims, strides, box, es,
                          CU_TENSOR_MAP_INTERLEAVE_NONE, CU_TENSOR_MAP_SWIZZLE_128B,
                          CU_TENSOR_MAP_L2_PROMOTION_L2_128B,
                          CU_TENSOR_MAP_FLOAT_OOB_FILL_NONE);
        tma_ok = (r1 == CUDA_SUCCESS && r2 == CUDA_SUCCESS);
    }

    if (tma_ok) {
        socnet_tma<<<GRID, TPB>>>(mIn, mOut, X, SC,
                                  w_init1, b_init1, w_init2, b_init2,
                                  w_eta1, b_eta1, w_eta2, b_eta2);
    } else {
        socnet_fb<<<N_ROWS / 4, 128>>>(X, SC,
                                       w_init1, b_init1, w_init2, b_init2,
                                       w_eta1, b_eta1, w_eta2, b_eta2, out);
    }
}

// round 11
// speedup vs baseline: 1.3921x; 1.0003x over previous
#include <cuda_runtime.h>
#include <cuda.h>
#include <cstdint>

#define L_LEN      4096
#define N_ROWS     4096
#define TPB        32                // 1 warp per CTA, one row per CTA
#define TILES      8                 // 8KB tiles per row
#define TILE_F4    512               // float4 per tile
#define TILE_BYTES 8192
#define YSTEP      64                // 128B-rows per tile
#define ROWY       512               // 128B-rows per data row
#define EPT        8                 // consecutive elements per thread per half
#define FULLM      0xFFFFFFFFu

// Fast, numerically safe softplus: max(x,0) + log(1 + e^{-|x|})
__device__ __forceinline__ float softplus_f(float x) {
    return fmaxf(x, 0.0f) + __logf(1.0f + __expf(-fabsf(x)));
}

__device__ __forceinline__ uint32_t smem_u32(const void* p) {
    return (uint32_t)__cvta_generic_to_shared(p);
}
__device__ __forceinline__ void mbar_init(uint32_t a, uint32_t cnt) {
    asm volatile("mbarrier.init.shared.b64 [%0], %1;" :: "r"(a), "r"(cnt) : "memory");
}
__device__ __forceinline__ void mbar_expect_tx(uint32_t a, uint32_t bytes) {
    asm volatile("mbarrier.arrive.expect_tx.shared.b64 _, [%0], %1;"
                 :: "r"(a), "r"(bytes) : "memory");
}
__device__ __forceinline__ void mbar_wait(uint32_t a, uint32_t parity) {
    asm volatile(
        "{\n\t.reg .pred P;\n\t"
        "W_%=:\n\t"
        "mbarrier.try_wait.parity.acquire.cta.shared::cta.b64 P, [%0], %1;\n\t"
        "@!P bra W_%=;\n\t}"
        :: "r"(a), "r"(parity) : "memory");
}
__device__ __forceinline__ void tma_load_seg(uint32_t dst, const CUtensorMap* m,
                                             int y, uint32_t mbar) {
    asm volatile("cp.async.bulk.tensor.2d.shared::cta.global.tile.mbarrier::complete_tx::bytes "
                 "[%0], [%1, {%2, %3}], [%4];"
                 :: "r"(dst), "l"(m), "r"(0), "r"(y), "r"(mbar) : "memory");
}
__device__ __forceinline__ void tma_store_seg(const CUtensorMap* m, int y, uint32_t src) {
    asm volatile("cp.async.bulk.tensor.2d.global.shared::cta.tile.bulk_group "
                 "[%0, {%1, %2}], [%3];"
                 :: "l"(m), "r"(0), "r"(y), "r"(src) : "memory");
}

__global__ __launch_bounds__(TPB)
void socnet_tma(const __grid_constant__ CUtensorMap tmap_in,
                const __grid_constant__ CUtensorMap tmap_out,
                const float* __restrict__ X,
                const float* __restrict__ SC,
                const float* __restrict__ w_init1, const float* __restrict__ b_init1,
                const float* __restrict__ w_init2, const float* __restrict__ b_init2,
                const float* __restrict__ w_eta1,  const float* __restrict__ b_eta1,
                const float* __restrict__ w_eta2,  const float* __restrict__ b_eta2) {
    // Static smem: 2x8KB in-ring + 1x8KB out + mbars = 24.6KB (< 48KB limit)
    __shared__ __align__(1024) float4 s_in[2][TILE_F4];
    __shared__ __align__(1024) float4 s_out[TILE_F4];
    __shared__ unsigned long long     s_mbar[2];

    const int lane = threadIdx.x;
    const int row  = blockIdx.x;
    const int ybase = row * ROWY;

    const float we0 = w_eta1[0], we1 = w_eta1[1], be1 = b_eta1[0];
    const float we2 = w_eta2[0], be2 = b_eta2[0];

    const uint32_t mb0  = smem_u32(&s_mbar[0]);
    const uint32_t mb1  = smem_u32(&s_mbar[1]);
    const uint32_t inb0 = smem_u32(&s_in[0][0]);
    const uint32_t inb1 = smem_u32(&s_in[1][0]);
    const uint32_t oub  = smem_u32(&s_out[0]);

    if (lane == 0) { mbar_init(mb0, 1); mbar_init(mb1, 1); }
    asm volatile("fence.proxy.async.shared::cta;" ::: "memory");
    __syncwarp();

    if (lane == 0) {
        mbar_expect_tx(mb0, TILE_BYTES);
        tma_load_seg(inb0, &tmap_in, ybase, mb0);
        mbar_expect_tx(mb1, TILE_BYTES);
        tma_load_seg(inb1, &tmap_in, ybase + YSTEP, mb1);
    }
    uint32_t ph0 = 0, ph1 = 0;

    // Per-row scalars: SC = [Q, eta0, R, cap]
    const float Q    = SC[row * 4 + 0];
    const float eta0 = SC[row * 4 + 1];
    const float R    = SC[row * 4 + 2];
    const float cap  = SC[row * 4 + 3];
    const float dscale = eta0 / (3600.0f * Q);

    const float4* __restrict__ Xg = reinterpret_cast<const float4*>(X) + (size_t)row * L_LEN;

    mbar_wait(mb0, 0); ph0 = 1;                      // tile 0 ready

    // soc_init from element 0 (swizzled offset 0, broadcast LDS)
    float4 x0 = s_in[0][0];
    float z = w_init1[0] * x0.y + w_init1[1] * x0.z
            + w_init1[2] * x0.w + w_init1[3] * R + b_init1[0];
    const float soc = cap * (1.0f + (w_init2[0] * softplus_f(z) + b_init2[0]));
    float bx = soc, by = soc, bz = soc, bw = soc;

    const int cswz = (lane & 7) << 4;                // SW128 XOR pattern

    #pragma unroll 1
    for (int t = 0; t < TILES; ++t) {
        const int b = t & 1;
        const char* ib = (const char*)&s_in[b][0];
        char*       ob = (char*)&s_out[0];

        // Tile boundary element (first elem of tile t+1) via global LDG,
        // issued before the wait; clamped for the final tile (masked later).
        float4 gbnd;
        const int bidx = (t + 1 < TILES) ? (t + 1) * TILE_F4 : (L_LEN - 1);
        if (lane == 31) gbnd = __ldg(&Xg[bidx]);

        if (t > 0) {                                 // wait own tile
            if (b) { mbar_wait(mb1, ph1); ph1 ^= 1; }
            else   { mbar_wait(mb0, ph0); ph0 ^= 1; }
        }
        // Out buffer reuse gate: previous tile's store must be read-drained
        if (lane == 0)
            asm volatile("cp.async.bulk.wait_group.read 0;" ::: "memory");
        __syncwarp();

        #pragma unroll
        for (int h = 0; h < 2; ++h) {
            const int rbase = ((h << 5) | lane) << 7;    // row (h*32+lane) * 128B

            // First element of this lane's 8
            float4 xc = *(const float4*)(ib + (rbase | cswz));
            float cI = xc.y, cT = xc.z, cU = xc.w;
            float cde = we2 * softplus_f(we0 * cI + we1 * cT + be1) + be2;

            // Neighbor of this lane's last element = next lane's first;
            // lane 31 gets the half/tile boundary.
            float nI  = __shfl_down_sync(FULLM, cI, 1);
            float nT  = __shfl_down_sync(FULLM, cT, 1);
            float nU  = __shfl_down_sync(FULLM, cU, 1);
            float nde = __shfl_down_sync(FULLM, cde, 1);
            if (lane == 31) {
                float4 bv;
                if (h == 0) bv = *(const float4*)(ib + 4096);  // elem 256 (swz=identity)
                else        bv = gbnd;
                nI = bv.y; nT = bv.z; nU = bv.w;
                nde = we2 * softplus_f(we0 * nI + we1 * nT + be1) + be2;
            }

            // Serial local exclusive prefixes; zero the nonexistent inc[L-1]
            const float lastmask =
                (t == TILES - 1 && h == 1 && lane == 31) ? 0.0f : 1.0f;
            float px[EPT], py[EPT], pz[EPT], pw[EPT];
            float tx = 0.f, ty = 0.f, tz = 0.f, tw = 0.f;
            #pragma unroll
            for (int k = 0; k < EPT; ++k) {
                px[k] = tx; py[k] = ty; pz[k] = tz; pw[k] = tw;
                float xI, xT, xU, xd;
                if (k < EPT - 1) {
                    float4 xn = *(const float4*)(ib + (rbase | (((k + 1) << 4) ^ cswz)));
                    xI = xn.y; xT = xn.z; xU = xn.w;
                    xd = we2 * softplus_f(we0 * xI + we1 * xT + be1) + be2;
                } else {
                    xI = nI; xT = nT; xU = nU; xd = nde;
                }
                float dy = dscale * (1.0f + cde) * cI;
                if (k == EPT - 1) dy *= lastmask;
                tx += dy * (xI - cI);
                ty += dy * (xT - cT);
                tz += dy * (xU - cU);
                tw += dy * (xd - cde);
                cI = xI; cT = xT; cU = xU; cde = xd;
            }

            // After half B consumed all inputs -> refill this buffer (tile t+2)
            if (h == 1) {
                __syncwarp();
                if (t + 2 < TILES && lane == 0) {
                    if (b) { mbar_expect_tx(mb1, TILE_BYTES);
                             tma_load_seg(inb1, &tmap_in, ybase + (t + 2) * YSTEP, mb1); }
                    else   { mbar_expect_tx(mb0, TILE_BYTES);
                             tma_load_seg(inb0, &tmap_in, ybase + (t + 2) * YSTEP, mb0); }
                }
            }

            // Warp scan of thread totals (once per 256 elements)
            float sx = tx, sy = ty, sz = tz, sw = tw;
            #pragma unroll
            for (int d = 1; d < 32; d <<= 1) {
                float ax = __shfl_up_sync(FULLM, sx, d);
                float ay = __shfl_up_sync(FULLM, sy, d);
                float az = __shfl_up_sync(FULLM, sz, d);
                float aw = __shfl_up_sync(FULLM, sw, d);
                if (lane >= d) { sx += ax; sy += ay; sz += az; sw += aw; }
            }
            float exx = __shfl_up_sync(FULLM, sx, 1);
            float exy = __shfl_up_sync(FULLM, sy, 1);
            float exz = __shfl_up_sync(FULLM, sz, 1);
            float exw = __shfl_up_sync(FULLM, sw, 1);
            if (lane == 0) { exx = exy = exz = exw = 0.f; }

            const float ox = bx + exx, oy = by + exy, oz = bz + exz, ow = bw + exw;
            #pragma unroll
            for (int k = 0; k < EPT; ++k) {
                float4 o;
                o.x = ox + px[k]; o.y = oy + py[k];
                o.z = oz + pz[k]; o.w = ow + pw[k];
                *(float4*)(ob + (rbase | ((k << 4) ^ cswz))) = o;
            }

            bx += __shfl_sync(FULLM, sx, 31);
            by += __shfl_sync(FULLM, sy, 31);
            bz += __shfl_sync(FULLM, sz, 31);
            bw += __shfl_sync(FULLM, sw, 31);
        }

        __syncwarp();
        if (lane == 0) {
            asm volatile("fence.proxy.async.shared::cta;" ::: "memory");
            tma_store_seg(&tmap_out, ybase + t * YSTEP, oub);
            asm volatile("cp.async.bulk.commit_group;" ::: "memory");
        }
    }

    if (lane == 0)
        asm volatile("cp.async.bulk.wait_group 0;" ::: "memory");
}

// ---------------- fallback kernel (proven R4 warp-scan, 131 us) ----------------
__global__ __launch_bounds__(128)
void socnet_fb(const float* __restrict__ X, const float* __restrict__ SC,
               const float* __restrict__ w_init1, const float* __restrict__ b_init1,
               const float* __restrict__ w_init2, const float* __restrict__ b_init2,
               const float* __restrict__ w_eta1,  const float* __restrict__ b_eta1,
               const float* __restrict__ w_eta2,  const float* __restrict__ b_eta2,
               float* __restrict__ out) {
    const int lane = threadIdx.x & 31;
    const int row  = blockIdx.x * 4 + (threadIdx.x >> 5);
    const float4* __restrict__ Xr = reinterpret_cast<const float4*>(X) + (size_t)row * L_LEN;
    float4* __restrict__ Or       = reinterpret_cast<float4*>(out)     + (size_t)row * L_LEN;
    const float Q = SC[row*4+0], eta0 = SC[row*4+1], R = SC[row*4+2], cap = SC[row*4+3];
    const float we0 = w_eta1[0], we1 = w_eta1[1], be1 = b_eta1[0];
    const float we2 = w_eta2[0], be2 = b_eta2[0];
    const float dscale = eta0 / (3600.0f * Q);
    float4 x0 = Xr[lane];
    float pI = x0.y, pT = x0.z, pU = x0.w;
    float pde = we2 * softplus_f(we0*pI + we1*pT + be1) + be2;
    const float I0 = __shfl_sync(FULLM, pI, 0);
    const float T0 = __shfl_sync(FULLM, pT, 0);
    const float U0 = __shfl_sync(FULLM, pU, 0);
    float z = w_init1[0]*I0 + w_init1[1]*T0 + w_init1[2]*U0 + w_init1[3]*R + b_init1[0];
    const float soc = cap * (1.0f + (w_init2[0]*softplus_f(z) + b_init2[0]));
    float bx = soc, by = soc, bz = soc, bw = soc;
    #pragma unroll 2
    for (int it = 0; it < L_LEN/32; ++it) {
        float nI, nT, nU, nde;
        if (it < L_LEN/32 - 1) {
            float4 xn = Xr[(it+1)*32 + lane];
            nI = xn.y; nT = xn.z; nU = xn.w;
            nde = we2 * softplus_f(we0*nI + we1*nT + be1) + be2;
        } else { nI = pI; nT = pT; nU = pU; nde = pde; }
        const int src = (lane + 1) & 31;
        const float qI  = __shfl_sync(FULLM, (lane==0)?nI :pI,  src);
        const float qT  = __shfl_sync(FULLM, (lane==0)?nT :pT,  src);
        const float qU  = __shfl_sync(FULLM, (lane==0)?nU :pU,  src);
        const float qde = __shfl_sync(FULLM, (lane==0)?nde:pde, src);
        const float dy = dscale * (1.0f + pde) * pI;
        float ex = dy*(qI-pI), ey = dy*(qT-pT), ez = dy*(qU-pU), ew = dy*(qde-pde);
        if (it == L_LEN/32 - 1 && lane == 31) { ex=ey=ez=ew=0.f; }
        float sx = ex, sy = ey, sz = ez, sw = ew;
        #pragma unroll
        for (int d = 1; d < 32; d <<= 1) {
            float ax = __shfl_up_sync(FULLM, sx, d);
            float ay = __shfl_up_sync(FULLM, sy, d);
            float az = __shfl_up_sync(FULLM, sz, d);
            float aw = __shfl_up_sync(FULLM, sw, d);
            if (lane >= d) { sx += ax; sy += ay; sz += az; sw += aw; }
        }
        float4 o;
        o.x = bx + (sx-ex); o.y = by + (sy-ey); o.z = bz + (sz-ez); o.w = bw + (sw-ew);
        Or[it*32 + lane] = o;
        bx += __shfl_sync(FULLM, sx, 31); by += __shfl_sync(FULLM, sy, 31);
        bz += __shfl_sync(FULLM, sz, 31); bw += __shfl_sync(FULLM, sw, 31);
        pI = nI; pT = nT; pU = nU; pde = nde;
    }
}

// ---------------- host ----------------
typedef CUresult (*PFN_encode)(CUtensorMap*, CUtensorMapDataType, cuuint32_t, void*,
                               const cuuint64_t*, const cuuint64_t*, const cuuint32_t*,
                               const cuuint32_t*, CUtensorMapInterleave, CUtensorMapSwizzle,
                               CUtensorMapL2promotion, CUtensorMapFloatOOBfill);

extern "C" void kernel_launch(void* const* d_in, const int* in_sizes, int n_in,
                              void* d_out, int out_size) {
    const float* X       = (const float*)d_in[0];
    const float* SC      = (const float*)d_in[1];
    const float* w_init1 = (const float*)d_in[2];
    const float* b_init1 = (const float*)d_in[3];
    const float* w_init2 = (const float*)d_in[4];
    const float* b_init2 = (const float*)d_in[5];
    const float* w_eta1  = (const float*)d_in[6];
    const float* b_eta1  = (const float*)d_in[7];
    const float* w_eta2  = (const float*)d_in[8];
    const float* b_eta2  = (const float*)d_in[9];
    float* out = (float*)d_out;

    void* fp = nullptr;
    cudaDriverEntryPointQueryResult qr;
    cudaGetDriverEntryPoint("cuTensorMapEncodeTiled", &fp,
                            cudaEnableDefault, &qr);

    bool tma_ok = false;
    CUtensorMap mIn, mOut;
    if (fp) {
        PFN_encode enc = (PFN_encode)fp;
        cuuint64_t dims[2]    = {32ull, (cuuint64_t)N_ROWS * ROWY};
        cuuint64_t strides[1] = {128ull};
        cuuint32_t box[2]     = {32u, (cuuint32_t)YSTEP};   // 8KB tile
        cuuint32_t es[2]      = {1u, 1u};
        CUresult r1 = enc(&mIn, CU_TENSOR_MAP_DATA_TYPE_FLOAT32, 2, (void*)X,
                          dims, strides, box, es,
                          CU_TENSOR_MAP_INTERLEAVE_NONE, CU_TENSOR_MAP_SWIZZLE_128B,
                          CU_TENSOR_MAP_L2_PROMOTION_L2_128B,
                          CU_TENSOR_MAP_FLOAT_OOB_FILL_NONE);
        CUresult r2 = enc(&mOut, CU_TENSOR_MAP_DATA_TYPE_FLOAT32, 2, (void*)out,
                          dims, strides, box, es,
                          CU_TENSOR_MAP_INTERLEAVE_NONE, CU_TENSOR_MAP_SWIZZLE_128B,
                          CU_TENSOR_MAP_L2_PROMOTION_L2_128B,
                          CU_TENSOR_MAP_FLOAT_OOB_FILL_NONE);
        tma_ok = (r1 == CUDA_SUCCESS && r2 == CUDA_SUCCESS);
    }

    if (tma_ok) {
        socnet_tma<<<N_ROWS, TPB>>>(mIn, mOut, X, SC,
                                    w_init1, b_init1, w_init2, b_init2,
                                    w_eta1, b_eta1, w_eta2, b_eta2);
    } else {
        socnet_fb<<<N_ROWS / 4, 128>>>(X, SC,
                                       w_init1, b_init1, w_init2, b_init2,
                                       w_eta1, b_eta1, w_eta2, b_eta2, out);
    }
}

// round 12
// speedup vs baseline: 1.4226x; 1.0219x over previous
#include <cuda_runtime.h>
#include <cuda.h>
#include <cstdint>

#define L_LEN      4096
#define N_ROWS     4096
#define TPB        32                // 1 warp per CTA, one row per CTA
#define TILES      8                 // 8KB input tiles per row
#define TILE_F4    512               // float4 per input tile
#define TILE_BYTES 8192
#define YSTEP      64                // 128B-rows per input tile
#define HSTEP      32                // 128B-rows per output half-tile (4KB)
#define ROWY       512               // 128B-rows per data row
#define EPT        8                 // consecutive elements per thread per half
#define FULLM      0xFFFFFFFFu

// Fast, numerically safe softplus: max(x,0) + log(1 + e^{-|x|})
__device__ __forceinline__ float softplus_f(float x) {
    return fmaxf(x, 0.0f) + __logf(1.0f + __expf(-fabsf(x)));
}

__device__ __forceinline__ uint32_t smem_u32(const void* p) {
    return (uint32_t)__cvta_generic_to_shared(p);
}
__device__ __forceinline__ void mbar_init(uint32_t a, uint32_t cnt) {
    asm volatile("mbarrier.init.shared.b64 [%0], %1;" :: "r"(a), "r"(cnt) : "memory");
}
__device__ __forceinline__ void mbar_expect_tx(uint32_t a, uint32_t bytes) {
    asm volatile("mbarrier.arrive.expect_tx.shared.b64 _, [%0], %1;"
                 :: "r"(a), "r"(bytes) : "memory");
}
__device__ __forceinline__ void mbar_wait(uint32_t a, uint32_t parity) {
    asm volatile(
        "{\n\t.reg .pred P;\n\t"
        "W_%=:\n\t"
        "mbarrier.try_wait.parity.acquire.cta.shared::cta.b64 P, [%0], %1;\n\t"
        "@!P bra W_%=;\n\t}"
        :: "r"(a), "r"(parity) : "memory");
}
__device__ __forceinline__ void tma_load_seg(uint32_t dst, const CUtensorMap* m,
                                             int y, uint32_t mbar) {
    asm volatile("cp.async.bulk.tensor.2d.shared::cta.global.tile.mbarrier::complete_tx::bytes "
                 "[%0], [%1, {%2, %3}], [%4];"
                 :: "r"(dst), "l"(m), "r"(0), "r"(y), "r"(mbar) : "memory");
}
__device__ __forceinline__ void tma_store_seg(const CUtensorMap* m, int y, uint32_t src) {
    asm volatile("cp.async.bulk.tensor.2d.global.shared::cta.tile.bulk_group "
                 "[%0, {%1, %2}], [%3];"
                 :: "l"(m), "r"(0), "r"(y), "r"(src) : "memory");
}

__global__ __launch_bounds__(TPB)
void socnet_tma(const __grid_constant__ CUtensorMap tmap_in,
                const __grid_constant__ CUtensorMap tmap_out,
                const float* __restrict__ X,
                const float* __restrict__ SC,
                const float* __restrict__ w_init1, const float* __restrict__ b_init1,
                const float* __restrict__ w_init2, const float* __restrict__ b_init2,
                const float* __restrict__ w_eta1,  const float* __restrict__ b_eta1,
                const float* __restrict__ w_eta2,  const float* __restrict__ b_eta2) {
    // Static smem: 3x8KB input ring + 1x4KB out = 28KB (+1KB reserve = 29KB
    // -> exactly 7 CTAs/SM: 1036 slots x 3.954 rows = even waves)
    __shared__ __align__(1024) float4 s_in[3][TILE_F4];
    __shared__ __align__(1024) float4 s_out[TILE_F4 / 2];
    __shared__ unsigned long long     s_mbar[3];

    const int lane = threadIdx.x;
    const int row  = blockIdx.x;
    const int ybase = row * ROWY;

    const float we0 = w_eta1[0], we1 = w_eta1[1], be1 = b_eta1[0];
    const float we2 = w_eta2[0], be2 = b_eta2[0];

    const uint32_t mbA  = smem_u32(&s_mbar[0]);
    const uint32_t mbB  = smem_u32(&s_mbar[1]);
    const uint32_t mbC  = smem_u32(&s_mbar[2]);
    const uint32_t inbA = smem_u32(&s_in[0][0]);
    const uint32_t inbB = smem_u32(&s_in[1][0]);
    const uint32_t inbC = smem_u32(&s_in[2][0]);
    const uint32_t oub  = smem_u32(&s_out[0]);

    if (lane == 0) { mbar_init(mbA, 1); mbar_init(mbB, 1); mbar_init(mbC, 1); }
    asm volatile("fence.proxy.async.shared::cta;" ::: "memory");
    __syncwarp();

    if (lane == 0) {
        mbar_expect_tx(mbA, TILE_BYTES);
        tma_load_seg(inbA, &tmap_in, ybase, mbA);
        mbar_expect_tx(mbB, TILE_BYTES);
        tma_load_seg(inbB, &tmap_in, ybase + YSTEP, mbB);
        mbar_expect_tx(mbC, TILE_BYTES);
        tma_load_seg(inbC, &tmap_in, ybase + 2 * YSTEP, mbC);
    }
    uint32_t phA = 0, phB = 0, phC = 0;

    // Per-row scalars: SC = [Q, eta0, R, cap]
    const float Q    = SC[row * 4 + 0];
    const float eta0 = SC[row * 4 + 1];
    const float R    = SC[row * 4 + 2];
    const float cap  = SC[row * 4 + 3];
    const float dscale = eta0 / (3600.0f * Q);

    const float4* __restrict__ Xg = reinterpret_cast<const float4*>(X) + (size_t)row * L_LEN;

    mbar_wait(mbA, 0); phA = 1;                      // tile 0 ready

    // soc_init from element 0 (swizzled offset 0, broadcast LDS)
    float4 x0 = s_in[0][0];
    float z = w_init1[0] * x0.y + w_init1[1] * x0.z
            + w_init1[2] * x0.w + w_init1[3] * R + b_init1[0];
    const float soc = cap * (1.0f + (w_init2[0] * softplus_f(z) + b_init2[0]));
    float bx = soc, by = soc, bz = soc, bw = soc;

    const int cswz = (lane & 7) << 4;                // SW128 XOR pattern

    #pragma unroll 1
    for (int g = 0; g < 3; ++g) {
        #pragma unroll
        for (int j = 0; j < 3; ++j) {
            const int t = g * 3 + j;                 // j compile-time -> buffer static
            if (t >= TILES) continue;

            const char* ib = (const char*)(j == 0 ? &s_in[0][0]
                                         : j == 1 ? &s_in[1][0] : &s_in[2][0]);
            const uint32_t mbJ  = (j == 0) ? mbA  : (j == 1) ? mbB  : mbC;
            const uint32_t inbJ = (j == 0) ? inbA : (j == 1) ? inbB : inbC;

            // Tile boundary element (first elem of tile t+1) via global LDG,
            // issued before the wait; clamped for the final tile (masked later).
            float4 gbnd;
            const int bidx = (t + 1 < TILES) ? (t + 1) * TILE_F4 : (L_LEN - 1);
            if (lane == 31) gbnd = __ldg(&Xg[bidx]);

            if (t > 0) {                             // wait own tile
                if (j == 0)      { mbar_wait(mbA, phA); phA ^= 1; }
                else if (j == 1) { mbar_wait(mbB, phB); phB ^= 1; }
                else             { mbar_wait(mbC, phC); phC ^= 1; }
            }

            #pragma unroll
            for (int h = 0; h < 2; ++h) {
                const int rbase = ((h << 5) | lane) << 7;   // in-row (h*32+lane)*128B
                const int obase = lane << 7;                // out-row lane*128B (4KB buf)

                // First element of this lane's 8
                float4 xc = *(const float4*)(ib + (rbase | cswz));
                float cI = xc.y, cT = xc.z, cU = xc.w;
                float cde = we2 * softplus_f(we0 * cI + we1 * cT + be1) + be2;

                // Neighbor of this lane's last element = next lane's first;
                // lane 31 gets the half/tile boundary.
                float nI  = __shfl_down_sync(FULLM, cI, 1);
                float nT  = __shfl_down_sync(FULLM, cT, 1);
                float nU  = __shfl_down_sync(FULLM, cU, 1);
                float nde = __shfl_down_sync(FULLM, cde, 1);
                if (lane == 31) {
                    float4 bv;
                    if (h == 0) bv = *(const float4*)(ib + 4096);  // elem 256 (swz id)
                    else        bv = gbnd;
                    nI = bv.y; nT = bv.z; nU = bv.w;
                    nde = we2 * softplus_f(we0 * nI + we1 * nT + be1) + be2;
                }

                // Serial local exclusive prefixes; zero the nonexistent inc[L-1]
                const float lastmask =
                    (t == TILES - 1 && h == 1 && lane == 31) ? 0.0f : 1.0f;
                float px[EPT], py[EPT], pz[EPT], pw[EPT];
                float tx = 0.f, ty = 0.f, tz = 0.f, tw = 0.f;
                #pragma unroll
                for (int k = 0; k < EPT; ++k) {
                    px[k] = tx; py[k] = ty; pz[k] = tz; pw[k] = tw;
                    float xI, xT, xU, xd;
                    if (k < EPT - 1) {
                        float4 xn = *(const float4*)(ib + (rbase | (((k + 1) << 4) ^ cswz)));
                        xI = xn.y; xT = xn.z; xU = xn.w;
                        xd = we2 * softplus_f(we0 * xI + we1 * xT + be1) + be2;
                    } else {
                        xI = nI; xT = nT; xU = nU; xd = nde;
                    }
                    float dy = dscale * (1.0f + cde) * cI;
                    if (k == EPT - 1) dy *= lastmask;
                    tx += dy * (xI - cI);
                    ty += dy * (xT - cT);
                    tz += dy * (xU - cU);
                    tw += dy * (xd - cde);
                    cI = xI; cT = xT; cU = xU; cde = xd;
                }

                // After half B consumed all inputs -> refill this buffer (tile t+3)
                if (h == 1) {
                    __syncwarp();
                    if (t + 3 < TILES && lane == 0) {
                        mbar_expect_tx(mbJ, TILE_BYTES);
                        tma_load_seg(inbJ, &tmap_in, ybase + (t + 3) * YSTEP, mbJ);
                    }
                }

                // Warp scan of thread totals (once per 256 elements)
                float sx = tx, sy = ty, sz = tz, sw = tw;
                #pragma unroll
                for (int d = 1; d < 32; d <<= 1) {
                    float ax = __shfl_up_sync(FULLM, sx, d);
                    float ay = __shfl_up_sync(FULLM, sy, d);
                    float az = __shfl_up_sync(FULLM, sz, d);
                    float aw = __shfl_up_sync(FULLM, sw, d);
                    if (lane >= d) { sx += ax; sy += ay; sz += az; sw += aw; }
                }
                float exx = __shfl_up_sync(FULLM, sx, 1);
                float exy = __shfl_up_sync(FULLM, sy, 1);
                float exz = __shfl_up_sync(FULLM, sz, 1);
                float exw = __shfl_up_sync(FULLM, sw, 1);
                if (lane == 0) { exx = exy = exz = exw = 0.f; }

                // Out buffer reuse gate: previous half's store must be read-drained
                if (lane == 0)
                    asm volatile("cp.async.bulk.wait_group.read 0;" ::: "memory");
                __syncwarp();

                char* ob = (char*)&s_out[0];
                const float ox = bx + exx, oy = by + exy, oz = bz + exz, ow = bw + exw;
                #pragma unroll
                for (int k = 0; k < EPT; ++k) {
                    float4 o;
                    o.x = ox + px[k]; o.y = oy + py[k];
                    o.z = oz + pz[k]; o.w = ow + pw[k];
                    *(float4*)(ob + (obase | ((k << 4) ^ cswz))) = o;
                }
                __syncwarp();
                if (lane == 0) {
                    asm volatile("fence.proxy.async.shared::cta;" ::: "memory");
                    tma_store_seg(&tmap_out, ybase + t * YSTEP + h * HSTEP, oub);
                    asm volatile("cp.async.bulk.commit_group;" ::: "memory");
                }

                bx += __shfl_sync(FULLM, sx, 31);
                by += __shfl_sync(FULLM, sy, 31);
                bz += __shfl_sync(FULLM, sz, 31);
                bw += __shfl_sync(FULLM, sw, 31);
            }
        }
    }

    if (lane == 0)
        asm volatile("cp.async.bulk.wait_group 0;" ::: "memory");
}

// ---------------- fallback kernel (proven R4 warp-scan, 131 us) ----------------
__global__ __launch_bounds__(128)
void socnet_fb(const float* __restrict__ X, const float* __restrict__ SC,
               const float* __restrict__ w_init1, const float* __restrict__ b_init1,
               const float* __restrict__ w_init2, const float* __restrict__ b_init2,
               const float* __restrict__ w_eta1,  const float* __restrict__ b_eta1,
               const float* __restrict__ w_eta2,  const float* __restrict__ b_eta2,
               float* __restrict__ out) {
    const int lane = threadIdx.x & 31;
    const int row  = blockIdx.x * 4 + (threadIdx.x >> 5);
    const float4* __restrict__ Xr = reinterpret_cast<const float4*>(X) + (size_t)row * L_LEN;
    float4* __restrict__ Or       = reinterpret_cast<float4*>(out)     + (size_t)row * L_LEN;
    const float Q = SC[row*4+0], eta0 = SC[row*4+1], R = SC[row*4+2], cap = SC[row*4+3];
    const float we0 = w_eta1[0], we1 = w_eta1[1], be1 = b_eta1[0];
    const float we2 = w_eta2[0], be2 = b_eta2[0];
    const float dscale = eta0 / (3600.0f * Q);
    float4 x0 = Xr[lane];
    float pI = x0.y, pT = x0.z, pU = x0.w;
    float pde = we2 * softplus_f(we0*pI + we1*pT + be1) + be2;
    const float I0 = __shfl_sync(FULLM, pI, 0);
    const float T0 = __shfl_sync(FULLM, pT, 0);
    const float U0 = __shfl_sync(FULLM, pU, 0);
    float z = w_init1[0]*I0 + w_init1[1]*T0 + w_init1[2]*U0 + w_init1[3]*R + b_init1[0];
    const float soc = cap * (1.0f + (w_init2[0]*softplus_f(z) + b_init2[0]));
    float bx = soc, by = soc, bz = soc, bw = soc;
    #pragma unroll 2
    for (int it = 0; it < L_LEN/32; ++it) {
        float nI, nT, nU, nde;
        if (it < L_LEN/32 - 1) {
            float4 xn = Xr[(it+1)*32 + lane];
            nI = xn.y; nT = xn.z; nU = xn.w;
            nde = we2 * softplus_f(we0*nI + we1*nT + be1) + be2;
        } else { nI = pI; nT = pT; nU = pU; nde = pde; }
        const int src = (lane + 1) & 31;
        const float qI  = __shfl_sync(FULLM, (lane==0)?nI :pI,  src);
        const float qT  = __shfl_sync(FULLM, (lane==0)?nT :pT,  src);
        const float qU  = __shfl_sync(FULLM, (lane==0)?nU :pU,  src);
        const float qde = __shfl_sync(FULLM, (lane==0)?nde:pde, src);
        const float dy = dscale * (1.0f + pde) * pI;
        float ex = dy*(qI-pI), ey = dy*(qT-pT), ez = dy*(qU-pU), ew = dy*(qde-pde);
        if (it == L_LEN/32 - 1 && lane == 31) { ex=ey=ez=ew=0.f; }
        float sx = ex, sy = ey, sz = ez, sw = ew;
        #pragma unroll
        for (int d = 1; d < 32; d <<= 1) {
            float ax = __shfl_up_sync(FULLM, sx, d);
            float ay = __shfl_up_sync(FULLM, sy, d);
            float az = __shfl_up_sync(FULLM, sz, d);
            float aw = __shfl_up_sync(FULLM, sw, d);
            if (lane >= d) { sx += ax; sy += ay; sz += az; sw += aw; }
        }
        float4 o;
        o.x = bx + (sx-ex); o.y = by + (sy-ey); o.z = bz + (sz-ez); o.w = bw + (sw-ew);
        Or[it*32 + lane] = o;
        bx += __shfl_sync(FULLM, sx, 31); by += __shfl_sync(FULLM, sy, 31);
        bz += __shfl_sync(FULLM, sz, 31); bw += __shfl_sync(FULLM, sw, 31);
        pI = nI; pT = nT; pU = nU; pde = nde;
    }
}

// ---------------- host ----------------
typedef CUresult (*PFN_encode)(CUtensorMap*, CUtensorMapDataType, cuuint32_t, void*,
                               const cuuint64_t*, const cuuint64_t*, const cuuint32_t*,
                               const cuuint32_t*, CUtensorMapInterleave, CUtensorMapSwizzle,
                               CUtensorMapL2promotion, CUtensorMapFloatOOBfill);

extern "C" void kernel_launch(void* const* d_in, const int* in_sizes, int n_in,
                              void* d_out, int out_size) {
    const float* X       = (const float*)d_in[0];
    const float* SC      = (const float*)d_in[1];
    const float* w_init1 = (const float*)d_in[2];
    const float* b_init1 = (const float*)d_in[3];
    const float* w_init2 = (const float*)d_in[4];
    const float* b_init2 = (const float*)d_in[5];
    const float* w_eta1  = (const float*)d_in[6];
    const float* b_eta1  = (const float*)d_in[7];
    const float* w_eta2  = (const float*)d_in[8];
    const float* b_eta2  = (const float*)d_in[9];
    float* out = (float*)d_out;

    void* fp = nullptr;
    cudaDriverEntryPointQueryResult qr;
    cudaGetDriverEntryPoint("cuTensorMapEncodeTiled", &fp,
                            cudaEnableDefault, &qr);

    bool tma_ok = false;
    CUtensorMap mIn, mOut;
    if (fp) {
        PFN_encode enc = (PFN_encode)fp;
        cuuint64_t dims[2]    = {32ull, (cuuint64_t)N_ROWS * ROWY};
        cuuint64_t strides[1] = {128ull};
        cuuint32_t boxIn[2]   = {32u, (cuuint32_t)YSTEP};   // 8KB tile
        cuuint32_t boxOut[2]  = {32u, (cuuint32_t)HSTEP};   // 4KB half-tile
        cuuint32_t es[2]      = {1u, 1u};
        CUresult r1 = enc(&mIn, CU_TENSOR_MAP_DATA_TYPE_FLOAT32, 2, (void*)X,
                          dims, strides, boxIn, es,
                          CU_TENSOR_MAP_INTERLEAVE_NONE, CU_TENSOR_MAP_SWIZZLE_128B,
                          CU_TENSOR_MAP_L2_PROMOTION_L2_128B,
                          CU_TENSOR_MAP_FLOAT_OOB_FILL_NONE);
        CUresult r2 = enc(&mOut, CU_TENSOR_MAP_DATA_TYPE_FLOAT32, 2, (void*)out,
                          dims, strides, boxOut, es,
                          CU_TENSOR_MAP_INTERLEAVE_NONE, CU_TENSOR_MAP_SWIZZLE_128B,
                          CU_TENSOR_MAP_L2_PROMOTION_L2_128B,
                          CU_TENSOR_MAP_FLOAT_OOB_FILL_NONE);
        tma_ok = (r1 == CUDA_SUCCESS && r2 == CUDA_SUCCESS);
    }

    if (tma_ok) {
        socnet_tma<<<N_ROWS, TPB>>>(mIn, mOut, X, SC,
                                    w_init1, b_init1, w_init2, b_init2,
                                    w_eta1, b_eta1, w_eta2, b_eta2);
    } else {
        socnet_fb<<<N_ROWS / 4, 128>>>(X, SC,
                                       w_init1, b_init1, w_init2, b_init2,
                                       w_eta1, b_eta1, w_eta2, b_eta2, out);
    }
}

// round 13
// speedup vs baseline: 1.4544x; 1.0224x over previous
#include <cuda_runtime.h>
#include <cuda.h>
#include <cstdint>

#define L_LEN      4096
#define N_ROWS     4096
#define TPB        32                // 1 warp per CTA, one row per CTA
#define TILES      8                 // 8KB input tiles per row
#define TILE_F4    512               // float4 per input tile
#define TILE_BYTES 8192
#define YSTEP      64                // 128B-rows per input tile
#define HSTEP      32                // 128B-rows per output half-tile (4KB)
#define ROWY       512               // 128B-rows per data row
#define EPT        8                 // consecutive elements per thread per half
#define FULLM      0xFFFFFFFFu

// Fast, numerically safe softplus: max(x,0) + log(1 + e^{-|x|})
__device__ __forceinline__ float softplus_f(float x) {
    return fmaxf(x, 0.0f) + __logf(1.0f + __expf(-fabsf(x)));
}

__device__ __forceinline__ uint32_t smem_u32(const void* p) {
    return (uint32_t)__cvta_generic_to_shared(p);
}
__device__ __forceinline__ void mbar_init(uint32_t a, uint32_t cnt) {
    asm volatile("mbarrier.init.shared.b64 [%0], %1;" :: "r"(a), "r"(cnt) : "memory");
}
__device__ __forceinline__ void mbar_expect_tx(uint32_t a, uint32_t bytes) {
    asm volatile("mbarrier.arrive.expect_tx.shared.b64 _, [%0], %1;"
                 :: "r"(a), "r"(bytes) : "memory");
}
__device__ __forceinline__ void mbar_wait(uint32_t a, uint32_t parity) {
    asm volatile(
        "{\n\t.reg .pred P;\n\t"
        "W_%=:\n\t"
        "mbarrier.try_wait.parity.acquire.cta.shared::cta.b64 P, [%0], %1;\n\t"
        "@!P bra W_%=;\n\t}"
        :: "r"(a), "r"(parity) : "memory");
}
__device__ __forceinline__ void tma_load_seg(uint32_t dst, const CUtensorMap* m,
                                             int y, uint32_t mbar) {
    asm volatile("cp.async.bulk.tensor.2d.shared::cta.global.tile.mbarrier::complete_tx::bytes "
                 "[%0], [%1, {%2, %3}], [%4];"
                 :: "r"(dst), "l"(m), "r"(0), "r"(y), "r"(mbar) : "memory");
}
__device__ __forceinline__ void tma_store_seg(const CUtensorMap* m, int y, uint32_t src) {
    asm volatile("cp.async.bulk.tensor.2d.global.shared::cta.tile.bulk_group "
                 "[%0, {%1, %2}], [%3];"
                 :: "l"(m), "r"(0), "r"(y), "r"(src) : "memory");
}

__global__ __launch_bounds__(TPB)
void socnet_tma(const __grid_constant__ CUtensorMap tmap_in,
                const __grid_constant__ CUtensorMap tmap_out,
                const float* __restrict__ X,
                const float* __restrict__ SC,
                const float* __restrict__ w_init1, const float* __restrict__ b_init1,
                const float* __restrict__ w_init2, const float* __restrict__ b_init2,
                const float* __restrict__ w_eta1,  const float* __restrict__ b_eta1,
                const float* __restrict__ w_eta2,  const float* __restrict__ b_eta2) {
    // Static smem: 3x8KB input ring + 2x4KB out = 32KB -> 6 CTAs/SM
    __shared__ __align__(1024) float4 s_in[3][TILE_F4];
    __shared__ __align__(1024) float4 s_out[2][TILE_F4 / 2];
    __shared__ unsigned long long     s_mbar[3];

    const int lane = threadIdx.x;
    const int row  = blockIdx.x;
    const int ybase = row * ROWY;

    const float we0 = w_eta1[0], we1 = w_eta1[1], be1 = b_eta1[0];
    const float we2 = w_eta2[0], be2 = b_eta2[0];

    const uint32_t mbA  = smem_u32(&s_mbar[0]);
    const uint32_t mbB  = smem_u32(&s_mbar[1]);
    const uint32_t mbC  = smem_u32(&s_mbar[2]);
    const uint32_t inbA = smem_u32(&s_in[0][0]);
    const uint32_t inbB = smem_u32(&s_in[1][0]);
    const uint32_t inbC = smem_u32(&s_in[2][0]);
    const uint32_t oub0 = smem_u32(&s_out[0][0]);
    const uint32_t oub1 = smem_u32(&s_out[1][0]);

    if (lane == 0) { mbar_init(mbA, 1); mbar_init(mbB, 1); mbar_init(mbC, 1); }
    asm volatile("fence.proxy.async.shared::cta;" ::: "memory");
    __syncwarp();

    if (lane == 0) {
        mbar_expect_tx(mbA, TILE_BYTES);
        tma_load_seg(inbA, &tmap_in, ybase, mbA);
        mbar_expect_tx(mbB, TILE_BYTES);
        tma_load_seg(inbB, &tmap_in, ybase + YSTEP, mbB);
        mbar_expect_tx(mbC, TILE_BYTES);
        tma_load_seg(inbC, &tmap_in, ybase + 2 * YSTEP, mbC);
    }
    uint32_t phA = 0, phB = 0, phC = 0;

    // Per-row scalars: SC = [Q, eta0, R, cap]
    const float Q    = SC[row * 4 + 0];
    const float eta0 = SC[row * 4 + 1];
    const float R    = SC[row * 4 + 2];
    const float cap  = SC[row * 4 + 3];
    const float dscale = eta0 / (3600.0f * Q);

    const float4* __restrict__ Xg = reinterpret_cast<const float4*>(X) + (size_t)row * L_LEN;

    mbar_wait(mbA, 0); phA = 1;                      // tile 0 ready

    // soc_init from element 0 (swizzled offset 0, broadcast LDS)
    float4 x0 = s_in[0][0];
    float z = w_init1[0] * x0.y + w_init1[1] * x0.z
            + w_init1[2] * x0.w + w_init1[3] * R + b_init1[0];
    const float soc = cap * (1.0f + (w_init2[0] * softplus_f(z) + b_init2[0]));
    float bx = soc, by = soc, bz = soc, bw = soc;

    const int cswz = (lane & 7) << 4;                // SW128 XOR pattern

    #pragma unroll 1
    for (int g = 0; g < 3; ++g) {
        #pragma unroll
        for (int j = 0; j < 3; ++j) {
            const int t = g * 3 + j;                 // j compile-time -> buffer static
            if (t >= TILES) continue;

            const char* ib = (const char*)(j == 0 ? &s_in[0][0]
                                         : j == 1 ? &s_in[1][0] : &s_in[2][0]);
            const uint32_t mbJ  = (j == 0) ? mbA  : (j == 1) ? mbB  : mbC;
            const uint32_t inbJ = (j == 0) ? inbA : (j == 1) ? inbB : inbC;

            // Tile boundary element (first elem of tile t+1) via global LDG,
            // issued before the wait; clamped for the final tile (masked later).
            float4 gbnd;
            const int bidx = (t + 1 < TILES) ? (t + 1) * TILE_F4 : (L_LEN - 1);
            if (lane == 31) gbnd = __ldg(&Xg[bidx]);

            if (t > 0) {                             // wait own tile
                if (j == 0)      { mbar_wait(mbA, phA); phA ^= 1; }
                else if (j == 1) { mbar_wait(mbB, phB); phB ^= 1; }
                else             { mbar_wait(mbC, phC); phC ^= 1; }
            }

            #pragma unroll
            for (int h = 0; h < 2; ++h) {
                const int rbase = ((h << 5) | lane) << 7;   // in-row (h*32+lane)*128B
                const int obase = lane << 7;                // out-row lane*128B (4KB buf)

                // First element of this lane's 8
                float4 xc = *(const float4*)(ib + (rbase | cswz));
                float cI = xc.y, cT = xc.z, cU = xc.w;
                float cde = we2 * softplus_f(we0 * cI + we1 * cT + be1) + be2;

                // Neighbor of this lane's last element = next lane's first;
                // lane 31 gets the half/tile boundary.
                float nI  = __shfl_down_sync(FULLM, cI, 1);
                float nT  = __shfl_down_sync(FULLM, cT, 1);
                float nU  = __shfl_down_sync(FULLM, cU, 1);
                float nde = __shfl_down_sync(FULLM, cde, 1);
                if (lane == 31) {
                    float4 bv;
                    if (h == 0) bv = *(const float4*)(ib + 4096);  // elem 256 (swz id)
                    else        bv = gbnd;
                    nI = bv.y; nT = bv.z; nU = bv.w;
                    nde = we2 * softplus_f(we0 * nI + we1 * nT + be1) + be2;
                }

                // Serial local exclusive prefixes; zero the nonexistent inc[L-1]
                const float lastmask =
                    (t == TILES - 1 && h == 1 && lane == 31) ? 0.0f : 1.0f;
                float px[EPT], py[EPT], pz[EPT], pw[EPT];
                float tx = 0.f, ty = 0.f, tz = 0.f, tw = 0.f;
                #pragma unroll
                for (int k = 0; k < EPT; ++k) {
                    px[k] = tx; py[k] = ty; pz[k] = tz; pw[k] = tw;
                    float xI, xT, xU, xd;
                    if (k < EPT - 1) {
                        float4 xn = *(const float4*)(ib + (rbase | (((k + 1) << 4) ^ cswz)));
                        xI = xn.y; xT = xn.z; xU = xn.w;
                        xd = we2 * softplus_f(we0 * xI + we1 * xT + be1) + be2;
                    } else {
                        xI = nI; xT = nT; xU = nU; xd = nde;
                    }
                    float dy = dscale * (1.0f + cde) * cI;
                    if (k == EPT - 1) dy *= lastmask;
                    tx += dy * (xI - cI);
                    ty += dy * (xT - cT);
                    tz += dy * (xU - cU);
                    tw += dy * (xd - cde);
                    cI = xI; cT = xT; cU = xU; cde = xd;
                }

                // After half B consumed all inputs -> refill this buffer (tile t+3)
                if (h == 1) {
                    __syncwarp();
                    if (t + 3 < TILES && lane == 0) {
                        mbar_expect_tx(mbJ, TILE_BYTES);
                        tma_load_seg(inbJ, &tmap_in, ybase + (t + 3) * YSTEP, mbJ);
                    }
                }

                // Warp scan of thread totals (once per 256 elements)
                float sx = tx, sy = ty, sz = tz, sw = tw;
                #pragma unroll
                for (int d = 1; d < 32; d <<= 1) {
                    float ax = __shfl_up_sync(FULLM, sx, d);
                    float ay = __shfl_up_sync(FULLM, sy, d);
                    float az = __shfl_up_sync(FULLM, sz, d);
                    float aw = __shfl_up_sync(FULLM, sw, d);
                    if (lane >= d) { sx += ax; sy += ay; sz += az; sw += aw; }
                }
                float exx = __shfl_up_sync(FULLM, sx, 1);
                float exy = __shfl_up_sync(FULLM, sy, 1);
                float exz = __shfl_up_sync(FULLM, sz, 1);
                float exw = __shfl_up_sync(FULLM, sw, 1);
                if (lane == 0) { exx = exy = exz = exw = 0.f; }

                // Double-buffered out halves: the store issued 2 halves ago on
                // this buffer must be read-drained (keep 1 outstanding group).
                if (lane == 0)
                    asm volatile("cp.async.bulk.wait_group.read 1;" ::: "memory");
                __syncwarp();

                char* ob = (char*)(h ? &s_out[1][0] : &s_out[0][0]);
                const float ox = bx + exx, oy = by + exy, oz = bz + exz, ow = bw + exw;
                #pragma unroll
                for (int k = 0; k < EPT; ++k) {
                    float4 o;
                    o.x = ox + px[k]; o.y = oy + py[k];
                    o.z = oz + pz[k]; o.w = ow + pw[k];
                    *(float4*)(ob + (obase | ((k << 4) ^ cswz))) = o;
                }
                __syncwarp();
                if (lane == 0) {
                    asm volatile("fence.proxy.async.shared::cta;" ::: "memory");
                    tma_store_seg(&tmap_out, ybase + t * YSTEP + h * HSTEP,
                                  h ? oub1 : oub0);
                    asm volatile("cp.async.bulk.commit_group;" ::: "memory");
                }

                bx += __shfl_sync(FULLM, sx, 31);
                by += __shfl_sync(FULLM, sy, 31);
                bz += __shfl_sync(FULLM, sz, 31);
                bw += __shfl_sync(FULLM, sw, 31);
            }
        }
    }

    if (lane == 0)
        asm volatile("cp.async.bulk.wait_group 0;" ::: "memory");
}

// ---------------- fallback kernel (proven R4 warp-scan, 131 us) ----------------
__global__ __launch_bounds__(128)
void socnet_fb(const float* __restrict__ X, const float* __restrict__ SC,
               const float* __restrict__ w_init1, const float* __restrict__ b_init1,
               const float* __restrict__ w_init2, const float* __restrict__ b_init2,
               const float* __restrict__ w_eta1,  const float* __restrict__ b_eta1,
               const float* __restrict__ w_eta2,  const float* __restrict__ b_eta2,
               float* __restrict__ out) {
    const int lane = threadIdx.x & 31;
    const int row  = blockIdx.x * 4 + (threadIdx.x >> 5);
    const float4* __restrict__ Xr = reinterpret_cast<const float4*>(X) + (size_t)row * L_LEN;
    float4* __restrict__ Or       = reinterpret_cast<float4*>(out)     + (size_t)row * L_LEN;
    const float Q = SC[row*4+0], eta0 = SC[row*4+1], R = SC[row*4+2], cap = SC[row*4+3];
    const float we0 = w_eta1[0], we1 = w_eta1[1], be1 = b_eta1[0];
    const float we2 = w_eta2[0], be2 = b_eta2[0];
    const float dscale = eta0 / (3600.0f * Q);
    float4 x0 = Xr[lane];
    float pI = x0.y, pT = x0.z, pU = x0.w;
    float pde = we2 * softplus_f(we0*pI + we1*pT + be1) + be2;
    const float I0 = __shfl_sync(FULLM, pI, 0);
    const float T0 = __shfl_sync(FULLM, pT, 0);
    const float U0 = __shfl_sync(FULLM, pU, 0);
    float z = w_init1[0]*I0 + w_init1[1]*T0 + w_init1[2]*U0 + w_init1[3]*R + b_init1[0];
    const float soc = cap * (1.0f + (w_init2[0]*softplus_f(z) + b_init2[0]));
    float bx = soc, by = soc, bz = soc, bw = soc;
    #pragma unroll 2
    for (int it = 0; it < L_LEN/32; ++it) {
        float nI, nT, nU, nde;
        if (it < L_LEN/32 - 1) {
            float4 xn = Xr[(it+1)*32 + lane];
            nI = xn.y; nT = xn.z; nU = xn.w;
            nde = we2 * softplus_f(we0*nI + we1*nT + be1) + be2;
        } else { nI = pI; nT = pT; nU = pU; nde = pde; }
        const int src = (lane + 1) & 31;
        const float qI  = __shfl_sync(FULLM, (lane==0)?nI :pI,  src);
        const float qT  = __shfl_sync(FULLM, (lane==0)?nT :pT,  src);
        const float qU  = __shfl_sync(FULLM, (lane==0)?nU :pU,  src);
        const float qde = __shfl_sync(FULLM, (lane==0)?nde:pde, src);
        const float dy = dscale * (1.0f + pde) * pI;
        float ex = dy*(qI-pI), ey = dy*(qT-pT), ez = dy*(qU-pU), ew = dy*(qde-pde);
        if (it == L_LEN/32 - 1 && lane == 31) { ex=ey=ez=ew=0.f; }
        float sx = ex, sy = ey, sz = ez, sw = ew;
        #pragma unroll
        for (int d = 1; d < 32; d <<= 1) {
            float ax = __shfl_up_sync(FULLM, sx, d);
            float ay = __shfl_up_sync(FULLM, sy, d);
            float az = __shfl_up_sync(FULLM, sz, d);
            float aw = __shfl_up_sync(FULLM, sw, d);
            if (lane >= d) { sx += ax; sy += ay; sz += az; sw += aw; }
        }
        float4 o;
        o.x = bx + (sx-ex); o.y = by + (sy-ey); o.z = bz + (sz-ez); o.w = bw + (sw-ew);
        Or[it*32 + lane] = o;
        bx += __shfl_sync(FULLM, sx, 31); by += __shfl_sync(FULLM, sy, 31);
        bz += __shfl_sync(FULLM, sz, 31); bw += __shfl_sync(FULLM, sw, 31);
        pI = nI; pT = nT; pU = nU; pde = nde;
    }
}

// ---------------- host ----------------
typedef CUresult (*PFN_encode)(CUtensorMap*, CUtensorMapDataType, cuuint32_t, void*,
                               const cuuint64_t*, const cuuint64_t*, const cuuint32_t*,
                               const cuuint32_t*, CUtensorMapInterleave, CUtensorMapSwizzle,
                               CUtensorMapL2promotion, CUtensorMapFloatOOBfill);

extern "C" void kernel_launch(void* const* d_in, const int* in_sizes, int n_in,
                              void* d_out, int out_size) {
    const float* X       = (const float*)d_in[0];
    const float* SC      = (const float*)d_in[1];
    const float* w_init1 = (const float*)d_in[2];
    const float* b_init1 = (const float*)d_in[3];
    const float* w_init2 = (const float*)d_in[4];
    const float* b_init2 = (const float*)d_in[5];
    const float* w_eta1  = (const float*)d_in[6];
    const float* b_eta1  = (const float*)d_in[7];
    const float* w_eta2  = (const float*)d_in[8];
    const float* b_eta2  = (const float*)d_in[9];
    float* out = (float*)d_out;

    void* fp = nullptr;
    cudaDriverEntryPointQueryResult qr;
    cudaGetDriverEntryPoint("cuTensorMapEncodeTiled", &fp,
                            cudaEnableDefault, &qr);

    bool tma_ok = false;
    CUtensorMap mIn, mOut;
    if (fp) {
        PFN_encode enc = (PFN_encode)fp;
        cuuint64_t dims[2]    = {32ull, (cuuint64_t)N_ROWS * ROWY};
        cuuint64_t strides[1] = {128ull};
        cuuint32_t boxIn[2]   = {32u, (cuuint32_t)YSTEP};   // 8KB tile
        cuuint32_t boxOut[2]  = {32u, (cuuint32_t)HSTEP};   // 4KB half-tile
        cuuint32_t es[2]      = {1u, 1u};
        CUresult r1 = enc(&mIn, CU_TENSOR_MAP_DATA_TYPE_FLOAT32, 2, (void*)X,
                          dims, strides, boxIn, es,
                          CU_TENSOR_MAP_INTERLEAVE_NONE, CU_TENSOR_MAP_SWIZZLE_128B,
                          CU_TENSOR_MAP_L2_PROMOTION_L2_256B,
                          CU_TENSOR_MAP_FLOAT_OOB_FILL_NONE);
        CUresult r2 = enc(&mOut, CU_TENSOR_MAP_DATA_TYPE_FLOAT32, 2, (void*)out,
                          dims, strides, boxOut, es,
                          CU_TENSOR_MAP_INTERLEAVE_NONE, CU_TENSOR_MAP_SWIZZLE_128B,
                          CU_TENSOR_MAP_L2_PROMOTION_L2_256B,
                          CU_TENSOR_MAP_FLOAT_OOB_FILL_NONE);
        tma_ok = (r1 == CUDA_SUCCESS && r2 == CUDA_SUCCESS);
    }

    if (tma_ok) {
        socnet_tma<<<N_ROWS, TPB>>>(mIn, mOut, X, SC,
                                    w_init1, b_init1, w_init2, b_init2,
                                    w_eta1, b_eta1, w_eta2, b_eta2);
    } else {
        socnet_fb<<<N_ROWS / 4, 128>>>(X, SC,
                                       w_init1, b_init1, w_init2, b_init2,
                                       w_eta1, b_eta1, w_eta2, b_eta2, out);
    }
}